// round 1
// baseline (speedup 1.0000x reference)
#include <cuda_runtime.h>
#include <math.h>

#define D 4096
#define NCLS 100
#define KSUP 5
#define QPER 75
#define ROWSPC 80           // k + q
#define NQ 7500
#define EPSC 1e-8f

// ---------------- scratch (static device globals, no allocs) ----------------
__device__ float g_proto[NCLS * D];      // class prototypes (mean of support)
__device__ float g_pn[NCLS * D];         // normalized prototypes
__device__ float g_an[NCLS * D];         // normalized adapted prototypes
__device__ float g_self[NCLS];           // sum(proto_n^2)
__device__ float g_qinv[NQ];             // 1 / clip(||query||, eps)
__device__ float g_presim[NQ * NCLS];    // cosine(query, proto)
__device__ int   g_label[NQ];            // argmax class per query

__device__ __forceinline__ int qrow(int j) {
    return (j / QPER) * ROWSPC + KSUP + (j % QPER);
}

// ---------------- block reductions ----------------
__device__ __forceinline__ float blk_sum(float v, float* sred) {
    int lane = threadIdx.x & 31, w = threadIdx.x >> 5;
#pragma unroll
    for (int o = 16; o > 0; o >>= 1) v += __shfl_down_sync(0xffffffffu, v, o);
    __syncthreads();
    if (lane == 0) sred[w] = v;
    __syncthreads();
    if (w == 0) {
        v = (lane < ((int)blockDim.x >> 5)) ? sred[lane] : 0.f;
#pragma unroll
        for (int o = 16; o > 0; o >>= 1) v += __shfl_down_sync(0xffffffffu, v, o);
        if (lane == 0) sred[0] = v;
    }
    __syncthreads();
    return sred[0];
}

__device__ __forceinline__ float blk_max(float v, float* sred) {
    int lane = threadIdx.x & 31, w = threadIdx.x >> 5;
#pragma unroll
    for (int o = 16; o > 0; o >>= 1) v = fmaxf(v, __shfl_down_sync(0xffffffffu, v, o));
    __syncthreads();
    if (lane == 0) sred[w] = v;
    __syncthreads();
    if (w == 0) {
        v = (lane < ((int)blockDim.x >> 5)) ? sred[lane] : -INFINITY;
#pragma unroll
        for (int o = 16; o > 0; o >>= 1) v = fmaxf(v, __shfl_down_sync(0xffffffffu, v, o));
        if (lane == 0) sred[0] = v;
    }
    __syncthreads();
    return sred[0];
}

// ---------------- 1) prototypes: mean(support), normalize, self_sim ----------------
__global__ void __launch_bounds__(256) proto_kernel(const float* __restrict__ x) {
    __shared__ float sred[32];
    int c = blockIdx.x;
    const float* sup = x + (size_t)c * ROWSPC * D;
    float ss = 0.f;
    for (int i = threadIdx.x; i < D; i += 256) {
        float s = (sup[i] + sup[D + i] + sup[2 * D + i] + sup[3 * D + i] + sup[4 * D + i]) * 0.2f;
        g_proto[c * D + i] = s;
        ss += s * s;
    }
    float tot = blk_sum(ss, sred);
    float inv = 1.f / fmaxf(sqrtf(tot), EPSC);
    float ss2 = 0.f;
    for (int i = threadIdx.x; i < D; i += 256) {
        float p = g_proto[c * D + i] * inv;
        g_pn[c * D + i] = p;
        ss2 += p * p;
    }
    float t2 = blk_sum(ss2, sred);
    if (threadIdx.x == 0) g_self[c] = t2;
}

// ---------------- 2) query inverse norms (one warp per query row) ----------------
__global__ void __launch_bounds__(256) qinv_kernel(const float* __restrict__ x) {
    int j = blockIdx.x * 8 + (threadIdx.x >> 5);
    int lane = threadIdx.x & 31;
    if (j >= NQ) return;
    const float4* r4 = (const float4*)(x + (size_t)qrow(j) * D);
    float ss = 0.f;
    for (int i = lane; i < D / 4; i += 32) {
        float4 v = r4[i];
        ss += v.x * v.x + v.y * v.y + v.z * v.z + v.w * v.w;
    }
#pragma unroll
    for (int o = 16; o > 0; o >>= 1) ss += __shfl_down_sync(0xffffffffu, ss, o);
    if (lane == 0) g_qinv[j] = 1.f / fmaxf(sqrtf(ss), EPSC);
}

// ---------------- 3)/6) fp32 SIMT GEMM: out[j,c] = dot(query_j, B_c) * qinv[j] (* tao) ----------------
#define GBM 32
#define GBN 128
#define GBK 32

template <int FINAL>
__global__ void __launch_bounds__(256) gemm_kernel(const float* __restrict__ x,
                                                   const float* __restrict__ Bm,
                                                   const float* __restrict__ taop,
                                                   float* __restrict__ out) {
    __shared__ __align__(16) float As[GBM][GBK];
    __shared__ __align__(16) float Bs[GBK][GBN];

    const int tid = threadIdx.x;
    const int tx = tid & 15;     // 16 col-groups of 8 -> 128 cols
    const int ty = tid >> 4;     // 16 row-groups of 2 -> 32 rows
    const int j0 = blockIdx.x * GBM;

    float acc[2][8];
#pragma unroll
    for (int i = 0; i < 2; i++)
#pragma unroll
        for (int jj = 0; jj < 8; jj++) acc[i][jj] = 0.f;

    const int mA = tid >> 3;     // 0..31 row in A tile
    const int wA = tid & 7;      // float4 slot within BK
    const int jA = j0 + mA;
    const float* arow = (jA < NQ) ? (x + (size_t)qrow(jA) * D + wA * 4) : (const float*)0;

    for (int k0 = 0; k0 < D; k0 += GBK) {
        float4 av = make_float4(0.f, 0.f, 0.f, 0.f);
        if (arow) av = *(const float4*)(arow + k0);
        float4 bv[4];
#pragma unroll
        for (int t = 0; t < 4; t++) {
            int f = tid + t * 256;
            int c = f >> 3, w = f & 7;
            if (c < NCLS) bv[t] = *(const float4*)(Bm + (size_t)c * D + k0 + w * 4);
            else          bv[t] = make_float4(0.f, 0.f, 0.f, 0.f);
        }
        __syncthreads();
        *(float4*)&As[mA][wA * 4] = av;
#pragma unroll
        for (int t = 0; t < 4; t++) {
            int f = tid + t * 256;
            int c = f >> 3, w = f & 7;
            Bs[w * 4 + 0][c] = bv[t].x;
            Bs[w * 4 + 1][c] = bv[t].y;
            Bs[w * 4 + 2][c] = bv[t].z;
            Bs[w * 4 + 3][c] = bv[t].w;
        }
        __syncthreads();
#pragma unroll
        for (int kk = 0; kk < GBK; kk++) {
            float a0 = As[ty * 2 + 0][kk];
            float a1 = As[ty * 2 + 1][kk];
            float4 b0 = *(const float4*)&Bs[kk][tx * 8];
            float4 b1 = *(const float4*)&Bs[kk][tx * 8 + 4];
            acc[0][0] += a0 * b0.x; acc[0][1] += a0 * b0.y; acc[0][2] += a0 * b0.z; acc[0][3] += a0 * b0.w;
            acc[0][4] += a0 * b1.x; acc[0][5] += a0 * b1.y; acc[0][6] += a0 * b1.z; acc[0][7] += a0 * b1.w;
            acc[1][0] += a1 * b0.x; acc[1][1] += a1 * b0.y; acc[1][2] += a1 * b0.z; acc[1][3] += a1 * b0.w;
            acc[1][4] += a1 * b1.x; acc[1][5] += a1 * b1.y; acc[1][6] += a1 * b1.z; acc[1][7] += a1 * b1.w;
        }
    }

    float taov = 1.f;
    if (FINAL) taov = taop[0];
#pragma unroll
    for (int i = 0; i < 2; i++) {
        int j = j0 + ty * 2 + i;
        if (j >= NQ) continue;
        float s = g_qinv[j] * taov;
#pragma unroll
        for (int jj = 0; jj < 8; jj++) {
            int c = tx * 8 + jj;
            if (c < NCLS) out[j * NCLS + c] = acc[i][jj] * s;
        }
    }
}

// ---------------- 4) argmax per query (one warp per row, first-index tie-break) ----------------
__global__ void __launch_bounds__(256) argmax_kernel() {
    int j = blockIdx.x * 8 + (threadIdx.x >> 5);
    int lane = threadIdx.x & 31;
    if (j >= NQ) return;
    const float* row = g_presim + j * NCLS;
    float best = -INFINITY;
    int bi = 0x7fffffff;
    for (int c = lane; c < NCLS; c += 32) {
        float v = row[c];
        if (v > best) { best = v; bi = c; }   // ascending scan: strict > keeps earliest
    }
#pragma unroll
    for (int o = 16; o > 0; o >>= 1) {
        float ov = __shfl_down_sync(0xffffffffu, best, o);
        int oi = __shfl_down_sync(0xffffffffu, bi, o);
        if (ov > best || (ov == best && oi < bi)) { best = ov; bi = oi; }
    }
    if (lane == 0) g_label[j] = bi;
}

// ---------------- 5) softmax over assigned queries + adapted prototype + normalize ----------------
#define MAXA 4096
__global__ void __launch_bounds__(256) adapt_kernel(const float* __restrict__ x) {
    __shared__ int   s_off[MAXA];
    __shared__ float s_w[MAXA];
    __shared__ float sred[32];
    __shared__ int   s_counts[257];

    int c = blockIdx.x, tid = threadIdx.x;

    // deterministic ordered gather of assigned query indices (ascending j)
    const int chunk = (NQ + 255) / 256;
    int jlo = tid * chunk, jhi = min(NQ, jlo + chunk);
    int cnt = 0;
    for (int j = jlo; j < jhi; j++) cnt += (g_label[j] == c);
    s_counts[tid] = cnt;
    __syncthreads();
    if (tid == 0) {
        int run = 0;
        for (int i = 0; i < 256; i++) { int v = s_counts[i]; s_counts[i] = run; run += v; }
        s_counts[256] = run;
    }
    __syncthreads();
    int pos = s_counts[tid];
    for (int j = jlo; j < jhi; j++)
        if (g_label[j] == c) { if (pos < MAXA) s_off[pos] = j; pos++; }
    int total = min(s_counts[256], MAXA);
    __syncthreads();

    // softmax max
    float m = g_self[c];
    for (int t = tid; t < total; t += 256) m = fmaxf(m, g_presim[s_off[t] * NCLS + c]);
    m = blk_max(m, sred);

    // exp + sum
    float se = 0.f;
    for (int t = tid; t < total; t += 256) {
        float e = expf(g_presim[s_off[t] * NCLS + c] - m);
        s_w[t] = e;
        se += e;
    }
    float eself = expf(g_self[c] - m);
    float Z = blk_sum(se, sred) + eself;
    float invZ = 1.f / Z;
    float wself = eself * invZ;
    for (int t = tid; t < total; t += 256) {
        s_w[t] *= invZ;
        s_off[t] = qrow(s_off[t]) * D;   // convert to row byte-offset base (elements)
    }
    __syncthreads();

    // adapted_proto[c, tid*16 .. +16) then normalize
    float accv[16];
#pragma unroll
    for (int s = 0; s < 16; s++) accv[s] = 0.f;
    for (int t = 0; t < total; t++) {
        float w = s_w[t];
        const float4* q4 = (const float4*)(x + s_off[t] + tid * 16);
#pragma unroll
        for (int v = 0; v < 4; v++) {
            float4 qv = q4[v];
            accv[v * 4 + 0] += w * qv.x;
            accv[v * 4 + 1] += w * qv.y;
            accv[v * 4 + 2] += w * qv.z;
            accv[v * 4 + 3] += w * qv.w;
        }
    }
    const float* pr = g_proto + (size_t)c * D + tid * 16;
    float ss = 0.f;
#pragma unroll
    for (int s = 0; s < 16; s++) {
        accv[s] += wself * pr[s];
        ss += accv[s] * accv[s];
    }
    float tot = blk_sum(ss, sred);
    float inv = 1.f / fmaxf(sqrtf(tot), EPSC);
    float* an = g_an + (size_t)c * D + tid * 16;
#pragma unroll
    for (int s = 0; s < 16; s++) an[s] = accv[s] * inv;
}

// ---------------- launch ----------------
extern "C" void kernel_launch(void* const* d_in, const int* in_sizes, int n_in,
                              void* d_out, int out_size) {
    const float* x   = (const float*)d_in[0];
    const float* tao = (const float*)d_in[1];
    float* out = (float*)d_out;

    float* presim; cudaGetSymbolAddress((void**)&presim, g_presim);
    float* pn;     cudaGetSymbolAddress((void**)&pn, g_pn);
    float* an;     cudaGetSymbolAddress((void**)&an, g_an);

    proto_kernel<<<NCLS, 256>>>(x);
    qinv_kernel<<<(NQ + 7) / 8, 256>>>(x);
    gemm_kernel<0><<<(NQ + GBM - 1) / GBM, 256>>>(x, pn, tao, presim);
    argmax_kernel<<<(NQ + 7) / 8, 256>>>();
    adapt_kernel<<<NCLS, 256>>>(x);
    gemm_kernel<1><<<(NQ + GBM - 1) / GBM, 256>>>(x, an, tao, out);
}

// round 2
// speedup vs baseline: 3.8312x; 3.8312x over previous
#include <cuda_runtime.h>
#include <math.h>

#define D 4096
#define NCLS 100
#define KSUP 5
#define QPER 75
#define ROWSPC 80
#define NQ 7500
#define EPSC 1e-8f

// ---------------- scratch ----------------
__device__ float g_proto[NCLS * D];
__device__ float g_pn[NCLS * D];
__device__ float g_pnh[NCLS * D];
__device__ float g_pnl[NCLS * D];
__device__ float g_an[NCLS * D];
__device__ float g_anh[NCLS * D];
__device__ float g_anl[NCLS * D];
__device__ float g_self[NCLS];
__device__ float g_qinv[NQ];
__device__ float g_presim[NQ * NCLS];
__device__ int   g_label[NQ];

__device__ __forceinline__ int qrow(int j) {
    return (j / QPER) * ROWSPC + KSUP + (j % QPER);
}

__device__ __forceinline__ unsigned f2tf(float f) {
    unsigned u;
    asm("cvt.rna.tf32.f32 %0, %1;" : "=r"(u) : "f"(f));
    return u;
}

// ---------------- block reductions ----------------
__device__ __forceinline__ float blk_sum(float v, float* sred) {
    int lane = threadIdx.x & 31, w = threadIdx.x >> 5;
#pragma unroll
    for (int o = 16; o > 0; o >>= 1) v += __shfl_down_sync(0xffffffffu, v, o);
    __syncthreads();
    if (lane == 0) sred[w] = v;
    __syncthreads();
    if (w == 0) {
        v = (lane < ((int)blockDim.x >> 5)) ? sred[lane] : 0.f;
#pragma unroll
        for (int o = 16; o > 0; o >>= 1) v += __shfl_down_sync(0xffffffffu, v, o);
        if (lane == 0) sred[0] = v;
    }
    __syncthreads();
    return sred[0];
}

__device__ __forceinline__ float blk_max(float v, float* sred) {
    int lane = threadIdx.x & 31, w = threadIdx.x >> 5;
#pragma unroll
    for (int o = 16; o > 0; o >>= 1) v = fmaxf(v, __shfl_down_sync(0xffffffffu, v, o));
    __syncthreads();
    if (lane == 0) sred[w] = v;
    __syncthreads();
    if (w == 0) {
        v = (lane < ((int)blockDim.x >> 5)) ? sred[lane] : -INFINITY;
#pragma unroll
        for (int o = 16; o > 0; o >>= 1) v = fmaxf(v, __shfl_down_sync(0xffffffffu, v, o));
        if (lane == 0) sred[0] = v;
    }
    __syncthreads();
    return sred[0];
}

// ---------------- 1) prototypes ----------------
__global__ void __launch_bounds__(256) proto_kernel(const float* __restrict__ x) {
    __shared__ float sred[32];
    int c = blockIdx.x;
    const float* sup = x + (size_t)c * ROWSPC * D;
    float ss = 0.f;
    for (int i = threadIdx.x; i < D; i += 256) {
        float s = (sup[i] + sup[D + i] + sup[2 * D + i] + sup[3 * D + i] + sup[4 * D + i]) * 0.2f;
        g_proto[c * D + i] = s;
        ss += s * s;
    }
    float tot = blk_sum(ss, sred);
    float inv = 1.f / fmaxf(sqrtf(tot), EPSC);
    float ss2 = 0.f;
    for (int i = threadIdx.x; i < D; i += 256) {
        float p = g_proto[c * D + i] * inv;
        g_pn[c * D + i] = p;
        ss2 += p * p;
    }
    float t2 = blk_sum(ss2, sred);
    if (threadIdx.x == 0) g_self[c] = t2;
}

// ---------------- tf32 split of a matrix ----------------
__global__ void __launch_bounds__(256) split_kernel(const float* __restrict__ src,
                                                    float* __restrict__ hi,
                                                    float* __restrict__ lo, int n) {
    int i = blockIdx.x * 256 + threadIdx.x;
    if (i >= n) return;
    float v = src[i];
    unsigned hu = f2tf(v);
    float hf = __uint_as_float(hu);
    hi[i] = hf;
    lo[i] = __uint_as_float(f2tf(v - hf));
}

// ---------------- 2) query inverse norms ----------------
__global__ void __launch_bounds__(256) qinv_kernel(const float* __restrict__ x) {
    int j = blockIdx.x * 8 + (threadIdx.x >> 5);
    int lane = threadIdx.x & 31;
    if (j >= NQ) return;
    const float4* r4 = (const float4*)(x + (size_t)qrow(j) * D);
    float ss = 0.f;
    for (int i = lane; i < D / 4; i += 32) {
        float4 v = r4[i];
        ss += v.x * v.x + v.y * v.y + v.z * v.z + v.w * v.w;
    }
#pragma unroll
    for (int o = 16; o > 0; o >>= 1) ss += __shfl_down_sync(0xffffffffu, ss, o);
    if (lane == 0) g_qinv[j] = 1.f / fmaxf(sqrtf(ss), EPSC);
}

// ---------------- 3)/6) tf32 mma GEMM ----------------
// out[j, c] = dot(x[qrow(j)], B[c]) * qinv[j] * (tao or 1)
// SPLIT3 = 1: 3xTF32 compensated (Ah*Bh + Ah*Bl + Al*Bh), tao = 1 (presim)
// SPLIT3 = 0: single tf32 (RNA-rounded operands), * tao (final)
#define BM 64
#define BN 128
#define BK 32
#define APAD 36           // padded row stride (floats) -> conflict-free frags
#define NIT (D / BK)      // 128

#define CPA16(dst, src, sz) \
    asm volatile("cp.async.cg.shared.global [%0], [%1], 16, %2;\n" :: "r"(dst), "l"(src), "r"(sz))

__device__ __forceinline__ void mma_tf32(float c[4], const unsigned a[4], const unsigned b[2]) {
    asm volatile(
        "mma.sync.aligned.m16n8k8.row.col.f32.tf32.tf32.f32 "
        "{%0,%1,%2,%3}, {%4,%5,%6,%7}, {%8,%9}, {%0,%1,%2,%3};\n"
        : "+f"(c[0]), "+f"(c[1]), "+f"(c[2]), "+f"(c[3])
        : "r"(a[0]), "r"(a[1]), "r"(a[2]), "r"(a[3]), "r"(b[0]), "r"(b[1]));
}

template <int SPLIT3>
__global__ void __launch_bounds__(256) mma_gemm(const float* __restrict__ x,
                                                const float* __restrict__ Bh,
                                                const float* __restrict__ Bl,
                                                const float* __restrict__ taop,
                                                float* __restrict__ out) {
    extern __shared__ float sm[];
    constexpr int SA = BM * APAD;                       // 2304
    constexpr int SB = BN * APAD;                       // 4608
    constexpr int SS = SA + SB + (SPLIT3 ? SB : 0);     // stage stride (floats)

    const int tid = threadIdx.x;
    const int lane = tid & 31;
    const int warp = tid >> 5;
    const int wM = warp >> 2;       // 0..1
    const int wN = warp & 3;        // 0..3
    const int g = lane >> 2;        // 0..7
    const int t4 = lane & 3;        // 0..3
    const int j0 = blockIdx.x * BM;

    float C[2][4][4];
#pragma unroll
    for (int mt = 0; mt < 2; mt++)
#pragma unroll
        for (int nt = 0; nt < 4; nt++)
#pragma unroll
            for (int r = 0; r < 4; r++) C[mt][nt][r] = 0.f;

    // precompute per-thread load descriptors
    const unsigned smbase = (unsigned)__cvta_generic_to_shared(sm);

    auto load_tile = [&](int stg, int k0) {
        unsigned abase = smbase + stg * SS * 4;
#pragma unroll
        for (int i = 0; i < BM * BK / 4 / 256; i++) {   // 2
            int idx = tid + i * 256;
            int row = idx >> 3, seg = idx & 7;
            int j = j0 + row;
            const float* src = x + (size_t)qrow(j < NQ ? j : NQ - 1) * D + k0 + seg * 4;
            unsigned dst = abase + (row * APAD + seg * 4) * 4;
            int sz = (j < NQ) ? 16 : 0;
            CPA16(dst, src, sz);
        }
        unsigned bhb = abase + SA * 4;
#pragma unroll
        for (int i = 0; i < BN * BK / 4 / 256; i++) {   // 4
            int idx = tid + i * 256;
            int n = idx >> 3, seg = idx & 7;
            const float* src = Bh + (size_t)(n < NCLS ? n : NCLS - 1) * D + k0 + seg * 4;
            unsigned dst = bhb + (n * APAD + seg * 4) * 4;
            int sz = (n < NCLS) ? 16 : 0;
            CPA16(dst, src, sz);
        }
        if (SPLIT3) {
            unsigned blb = abase + (SA + SB) * 4;
#pragma unroll
            for (int i = 0; i < BN * BK / 4 / 256; i++) {
                int idx = tid + i * 256;
                int n = idx >> 3, seg = idx & 7;
                const float* src = Bl + (size_t)(n < NCLS ? n : NCLS - 1) * D + k0 + seg * 4;
                unsigned dst = blb + (n * APAD + seg * 4) * 4;
                int sz = (n < NCLS) ? 16 : 0;
                CPA16(dst, src, sz);
            }
        }
        asm volatile("cp.async.commit_group;\n");
    };

    load_tile(0, 0);

    for (int it = 0; it < NIT; it++) {
        asm volatile("cp.async.wait_group 0;\n");
        __syncthreads();
        if (it + 1 < NIT) load_tile((it + 1) & 1, (it + 1) * BK);

        const float* As = sm + (it & 1) * SS;
        const float* Bhs = As + SA;
        const float* Bls = Bhs + SB;

#pragma unroll
        for (int step = 0; step < 4; step++) {
            const int k = step * 8 + t4;
            unsigned ah[2][4], al[2][4];
#pragma unroll
            for (int mt = 0; mt < 2; mt++) {
                int r0 = wM * 32 + mt * 16 + g;
                float v0 = As[r0 * APAD + k];
                float v1 = As[(r0 + 8) * APAD + k];
                float v2 = As[r0 * APAD + k + 4];
                float v3 = As[(r0 + 8) * APAD + k + 4];
                ah[mt][0] = f2tf(v0); ah[mt][1] = f2tf(v1);
                ah[mt][2] = f2tf(v2); ah[mt][3] = f2tf(v3);
                if (SPLIT3) {
                    al[mt][0] = f2tf(v0 - __uint_as_float(ah[mt][0]));
                    al[mt][1] = f2tf(v1 - __uint_as_float(ah[mt][1]));
                    al[mt][2] = f2tf(v2 - __uint_as_float(ah[mt][2]));
                    al[mt][3] = f2tf(v3 - __uint_as_float(ah[mt][3]));
                }
            }
            unsigned bh[4][2], bl[4][2];
#pragma unroll
            for (int nt = 0; nt < 4; nt++) {
                int n0 = wN * 32 + nt * 8 + g;
                bh[nt][0] = __float_as_uint(Bhs[n0 * APAD + k]);
                bh[nt][1] = __float_as_uint(Bhs[n0 * APAD + k + 4]);
                if (SPLIT3) {
                    bl[nt][0] = __float_as_uint(Bls[n0 * APAD + k]);
                    bl[nt][1] = __float_as_uint(Bls[n0 * APAD + k + 4]);
                }
            }
#pragma unroll
            for (int mt = 0; mt < 2; mt++)
#pragma unroll
                for (int nt = 0; nt < 4; nt++) {
                    mma_tf32(C[mt][nt], ah[mt], bh[nt]);
                    if (SPLIT3) {
                        mma_tf32(C[mt][nt], ah[mt], bl[nt]);
                        mma_tf32(C[mt][nt], al[mt], bh[nt]);
                    }
                }
        }
        __syncthreads();
    }

    const float taov = SPLIT3 ? 1.f : taop[0];
#pragma unroll
    for (int mt = 0; mt < 2; mt++) {
        int r0 = wM * 32 + mt * 16 + g;
#pragma unroll
        for (int half = 0; half < 2; half++) {
            int j = j0 + r0 + half * 8;
            if (j >= NQ) continue;
            float s = g_qinv[j] * taov;
#pragma unroll
            for (int nt = 0; nt < 4; nt++) {
                int c = wN * 32 + nt * 8 + 2 * t4;
                if (c < NCLS)     out[j * NCLS + c]     = C[mt][nt][half * 2 + 0] * s;
                if (c + 1 < NCLS) out[j * NCLS + c + 1] = C[mt][nt][half * 2 + 1] * s;
            }
        }
    }
}

// ---------------- 4) argmax per query ----------------
__global__ void __launch_bounds__(256) argmax_kernel() {
    int j = blockIdx.x * 8 + (threadIdx.x >> 5);
    int lane = threadIdx.x & 31;
    if (j >= NQ) return;
    const float* row = g_presim + j * NCLS;
    float best = -INFINITY;
    int bi = 0x7fffffff;
    for (int c = lane; c < NCLS; c += 32) {
        float v = row[c];
        if (v > best) { best = v; bi = c; }
    }
#pragma unroll
    for (int o = 16; o > 0; o >>= 1) {
        float ov = __shfl_down_sync(0xffffffffu, best, o);
        int oi = __shfl_down_sync(0xffffffffu, bi, o);
        if (ov > best || (ov == best && oi < bi)) { best = ov; bi = oi; }
    }
    if (lane == 0) g_label[j] = bi;
}

// ---------------- 5) softmax + adapted prototype ----------------
#define MAXA 4096
__global__ void __launch_bounds__(256) adapt_kernel(const float* __restrict__ x) {
    __shared__ int   s_off[MAXA];
    __shared__ float s_w[MAXA];
    __shared__ float sred[32];
    __shared__ int   s_counts[257];

    int c = blockIdx.x, tid = threadIdx.x;

    const int chunk = (NQ + 255) / 256;
    int jlo = tid * chunk, jhi = min(NQ, jlo + chunk);
    int cnt = 0;
    for (int j = jlo; j < jhi; j++) cnt += (g_label[j] == c);
    s_counts[tid] = cnt;
    __syncthreads();
    if (tid == 0) {
        int run = 0;
        for (int i = 0; i < 256; i++) { int v = s_counts[i]; s_counts[i] = run; run += v; }
        s_counts[256] = run;
    }
    __syncthreads();
    int pos = s_counts[tid];
    for (int j = jlo; j < jhi; j++)
        if (g_label[j] == c) { if (pos < MAXA) s_off[pos] = j; pos++; }
    int total = min(s_counts[256], MAXA);
    __syncthreads();

    float m = g_self[c];
    for (int t = tid; t < total; t += 256) m = fmaxf(m, g_presim[s_off[t] * NCLS + c]);
    m = blk_max(m, sred);

    float se = 0.f;
    for (int t = tid; t < total; t += 256) {
        float e = expf(g_presim[s_off[t] * NCLS + c] - m);
        s_w[t] = e;
        se += e;
    }
    float eself = expf(g_self[c] - m);
    float Z = blk_sum(se, sred) + eself;
    float invZ = 1.f / Z;
    float wself = eself * invZ;
    for (int t = tid; t < total; t += 256) {
        s_w[t] *= invZ;
        s_off[t] = qrow(s_off[t]) * D;
    }
    __syncthreads();

    float accv[16];
#pragma unroll
    for (int s = 0; s < 16; s++) accv[s] = 0.f;
    for (int t = 0; t < total; t++) {
        float w = s_w[t];
        const float4* q4 = (const float4*)(x + s_off[t] + tid * 16);
#pragma unroll
        for (int v = 0; v < 4; v++) {
            float4 qv = q4[v];
            accv[v * 4 + 0] += w * qv.x;
            accv[v * 4 + 1] += w * qv.y;
            accv[v * 4 + 2] += w * qv.z;
            accv[v * 4 + 3] += w * qv.w;
        }
    }
    const float* pr = g_proto + (size_t)c * D + tid * 16;
    float ss = 0.f;
#pragma unroll
    for (int s = 0; s < 16; s++) {
        accv[s] += wself * pr[s];
        ss += accv[s] * accv[s];
    }
    float tot = blk_sum(ss, sred);
    float inv = 1.f / fmaxf(sqrtf(tot), EPSC);
    float* an = g_an + (size_t)c * D + tid * 16;
#pragma unroll
    for (int s = 0; s < 16; s++) an[s] = accv[s] * inv;
}

// ---------------- launch ----------------
extern "C" void kernel_launch(void* const* d_in, const int* in_sizes, int n_in,
                              void* d_out, int out_size) {
    const float* x   = (const float*)d_in[0];
    const float* tao = (const float*)d_in[1];
    float* out = (float*)d_out;

    float *presim, *pn, *pnh, *pnl, *an, *anh, *anl;
    cudaGetSymbolAddress((void**)&presim, g_presim);
    cudaGetSymbolAddress((void**)&pn,  g_pn);
    cudaGetSymbolAddress((void**)&pnh, g_pnh);
    cudaGetSymbolAddress((void**)&pnl, g_pnl);
    cudaGetSymbolAddress((void**)&an,  g_an);
    cudaGetSymbolAddress((void**)&anh, g_anh);
    cudaGetSymbolAddress((void**)&anl, g_anl);

    const int smem1 = 2 * (BM * APAD + 2 * BN * APAD) * 4;   // 92160 B (3x split)
    const int smem0 = 2 * (BM * APAD + BN * APAD) * 4;       // 55296 B
    cudaFuncSetAttribute(mma_gemm<1>, cudaFuncAttributeMaxDynamicSharedMemorySize, smem1);
    cudaFuncSetAttribute(mma_gemm<0>, cudaFuncAttributeMaxDynamicSharedMemorySize, smem0);

    const int nblk = (NQ + BM - 1) / BM;   // 118

    proto_kernel<<<NCLS, 256>>>(x);
    split_kernel<<<(NCLS * D + 255) / 256, 256>>>(pn, pnh, pnl, NCLS * D);
    qinv_kernel<<<(NQ + 7) / 8, 256>>>(x);
    mma_gemm<1><<<nblk, 256, smem1>>>(x, pnh, pnl, tao, presim);
    argmax_kernel<<<(NQ + 7) / 8, 256>>>();
    adapt_kernel<<<NCLS, 256>>>(x);
    split_kernel<<<(NCLS * D + 255) / 256, 256>>>(an, anh, anl, NCLS * D);
    mma_gemm<0><<<nblk, 256, smem0>>>(x, anh, anl, tao, out);
}

// round 3
// speedup vs baseline: 4.0375x; 1.0538x over previous
#include <cuda_runtime.h>
#include <math.h>

#define D 4096
#define NCLS 100
#define KSUP 5
#define QPER 75
#define ROWSPC 80
#define NQ 7500
#define EPSC 1e-8f
#define GAPT 2e-4f
#define MAXC 8

// ---------------- scratch ----------------
__device__ float g_xt[NQ * D];          // tf32-rounded queries, linearized
__device__ float g_proto[NCLS * D];
__device__ float g_pn[NCLS * D];        // exact fp32 normalized protos (for refine)
__device__ float g_pnh[NCLS * D];       // tf32-rounded pn (for gemm)
__device__ float g_anh[NCLS * D];       // tf32-rounded adapted protos
__device__ float g_self[NCLS];
__device__ float g_qinv[NQ];
__device__ float g_presim[NQ * NCLS];
__device__ float g_win[NQ];             // exact winner sim per query
__device__ int   g_label[NQ];
__device__ int   g_cand[NQ * MAXC];
__device__ int   g_ncand[NQ];

__device__ __forceinline__ int qrow(int j) {
    return (j / QPER) * ROWSPC + KSUP + (j % QPER);
}

__device__ __forceinline__ float f2tff(float f) {
    unsigned u;
    asm("cvt.rna.tf32.f32 %0, %1;" : "=r"(u) : "f"(f));
    return __uint_as_float(u);
}

// ---------------- block reductions ----------------
__device__ __forceinline__ float blk_sum(float v, float* sred) {
    int lane = threadIdx.x & 31, w = threadIdx.x >> 5;
#pragma unroll
    for (int o = 16; o > 0; o >>= 1) v += __shfl_down_sync(0xffffffffu, v, o);
    __syncthreads();
    if (lane == 0) sred[w] = v;
    __syncthreads();
    if (w == 0) {
        v = (lane < ((int)blockDim.x >> 5)) ? sred[lane] : 0.f;
#pragma unroll
        for (int o = 16; o > 0; o >>= 1) v += __shfl_down_sync(0xffffffffu, v, o);
        if (lane == 0) sred[0] = v;
    }
    __syncthreads();
    return sred[0];
}

__device__ __forceinline__ float blk_max(float v, float* sred) {
    int lane = threadIdx.x & 31, w = threadIdx.x >> 5;
#pragma unroll
    for (int o = 16; o > 0; o >>= 1) v = fmaxf(v, __shfl_down_sync(0xffffffffu, v, o));
    __syncthreads();
    if (lane == 0) sred[w] = v;
    __syncthreads();
    if (w == 0) {
        v = (lane < ((int)blockDim.x >> 5)) ? sred[lane] : -INFINITY;
#pragma unroll
        for (int o = 16; o > 0; o >>= 1) v = fmaxf(v, __shfl_down_sync(0xffffffffu, v, o));
        if (lane == 0) sred[0] = v;
    }
    __syncthreads();
    return sred[0];
}

// ---------------- 1) prototypes: mean, normalize, self_sim, tf32 copy ----------------
__global__ void __launch_bounds__(256) proto_kernel(const float* __restrict__ x) {
    __shared__ float sred[32];
    int c = blockIdx.x;
    const float* sup = x + (size_t)c * ROWSPC * D;
    float ss = 0.f;
    for (int i = threadIdx.x; i < D; i += 256) {
        float s = (sup[i] + sup[D + i] + sup[2 * D + i] + sup[3 * D + i] + sup[4 * D + i]) * 0.2f;
        g_proto[c * D + i] = s;
        ss += s * s;
    }
    float tot = blk_sum(ss, sred);
    float inv = 1.f / fmaxf(sqrtf(tot), EPSC);
    float ss2 = 0.f;
    for (int i = threadIdx.x; i < D; i += 256) {
        float p = g_proto[c * D + i] * inv;
        g_pn[c * D + i] = p;
        g_pnh[c * D + i] = f2tff(p);
        ss2 += p * p;
    }
    float t2 = blk_sum(ss2, sred);
    if (threadIdx.x == 0) g_self[c] = t2;
}

// ---------------- 2) pack queries: tf32 round + linearize + qinv ----------------
__global__ void __launch_bounds__(128) pack_kernel(const float* __restrict__ x) {
    __shared__ float sred[32];
    int j = blockIdx.x;
    const float4* src = (const float4*)(x + (size_t)qrow(j) * D);
    float4* dst = (float4*)(g_xt + (size_t)j * D);
    float ss = 0.f;
#pragma unroll 4
    for (int i = threadIdx.x; i < D / 4; i += 128) {
        float4 v = src[i];
        ss += v.x * v.x + v.y * v.y + v.z * v.z + v.w * v.w;
        float4 r;
        r.x = f2tff(v.x); r.y = f2tff(v.y); r.z = f2tff(v.z); r.w = f2tff(v.w);
        dst[i] = r;
    }
    float tot = blk_sum(ss, sred);
    if (threadIdx.x == 0) g_qinv[j] = 1.f / fmaxf(sqrtf(tot), EPSC);
}

// ---------------- 3)/7) single-tf32 mma GEMM ----------------
// out[j, c] = dot(A_j, B_c) * qinv[j] * (tao if FIN)
#define BM 32
#define BN 128
#define BK 32
#define APAD 36
#define NIT (D / BK)

#define CPA16(dst, src, sz) \
    asm volatile("cp.async.cg.shared.global [%0], [%1], 16, %2;\n" :: "r"(dst), "l"(src), "r"(sz))

__device__ __forceinline__ void mma_tf32(float c[4], const unsigned a[4], const unsigned b[2]) {
    asm volatile(
        "mma.sync.aligned.m16n8k8.row.col.f32.tf32.tf32.f32 "
        "{%0,%1,%2,%3}, {%4,%5,%6,%7}, {%8,%9}, {%0,%1,%2,%3};\n"
        : "+f"(c[0]), "+f"(c[1]), "+f"(c[2]), "+f"(c[3])
        : "r"(a[0]), "r"(a[1]), "r"(a[2]), "r"(a[3]), "r"(b[0]), "r"(b[1]));
}

template <int FIN>
__global__ void __launch_bounds__(128, 4) mma_gemm(const float* __restrict__ A,
                                                   const float* __restrict__ B,
                                                   const float* __restrict__ taop,
                                                   float* __restrict__ out) {
    extern __shared__ float sm[];
    constexpr int SA = BM * APAD;        // 1152
    constexpr int SB = BN * APAD;        // 4608
    constexpr int SS = SA + SB;          // 5760 floats/stage

    const int tid = threadIdx.x;
    const int lane = tid & 31;
    const int wN = tid >> 5;             // 0..3
    const int g = lane >> 2;
    const int t4 = lane & 3;
    const int j0 = blockIdx.x * BM;

    float C[2][4][4];
#pragma unroll
    for (int mt = 0; mt < 2; mt++)
#pragma unroll
        for (int nt = 0; nt < 4; nt++)
#pragma unroll
            for (int r = 0; r < 4; r++) C[mt][nt][r] = 0.f;

    const unsigned smbase = (unsigned)__cvta_generic_to_shared(sm);

    auto load_tile = [&](int stg, int k0) {
        unsigned abase = smbase + stg * SS * 4;
#pragma unroll
        for (int i = 0; i < 2; i++) {               // A: 32x32 = 256 float4
            int idx = tid + i * 128;
            int row = idx >> 3, seg = idx & 7;
            int j = j0 + row;
            const float* src = A + (size_t)(j < NQ ? j : NQ - 1) * D + k0 + seg * 4;
            unsigned dst = abase + (row * APAD + seg * 4) * 4;
            CPA16(dst, src, (j < NQ) ? 16 : 0);
        }
        unsigned bbase = abase + SA * 4;
#pragma unroll
        for (int i = 0; i < 8; i++) {               // B: 128x32 = 1024 float4
            int idx = tid + i * 128;
            int n = idx >> 3, seg = idx & 7;
            const float* src = B + (size_t)(n < NCLS ? n : NCLS - 1) * D + k0 + seg * 4;
            unsigned dst = bbase + (n * APAD + seg * 4) * 4;
            CPA16(dst, src, (n < NCLS) ? 16 : 0);
        }
        asm volatile("cp.async.commit_group;\n");
    };

    load_tile(0, 0);

    for (int it = 0; it < NIT; it++) {
        asm volatile("cp.async.wait_group 0;\n");
        __syncthreads();
        if (it + 1 < NIT) load_tile((it + 1) & 1, (it + 1) * BK);

        const float* As = sm + (it & 1) * SS;
        const float* Bs = As + SA;

#pragma unroll
        for (int step = 0; step < 4; step++) {
            const int k = step * 8 + t4;
            unsigned a[2][4];
#pragma unroll
            for (int mt = 0; mt < 2; mt++) {
                int r0 = mt * 16 + g;
                a[mt][0] = __float_as_uint(As[r0 * APAD + k]);
                a[mt][1] = __float_as_uint(As[(r0 + 8) * APAD + k]);
                a[mt][2] = __float_as_uint(As[r0 * APAD + k + 4]);
                a[mt][3] = __float_as_uint(As[(r0 + 8) * APAD + k + 4]);
            }
            unsigned b[4][2];
#pragma unroll
            for (int nt = 0; nt < 4; nt++) {
                int n0 = wN * 32 + nt * 8 + g;
                b[nt][0] = __float_as_uint(Bs[n0 * APAD + k]);
                b[nt][1] = __float_as_uint(Bs[n0 * APAD + k + 4]);
            }
#pragma unroll
            for (int mt = 0; mt < 2; mt++)
#pragma unroll
                for (int nt = 0; nt < 4; nt++)
                    mma_tf32(C[mt][nt], a[mt], b[nt]);
        }
        __syncthreads();
    }

    const float taov = FIN ? taop[0] : 1.f;
#pragma unroll
    for (int mt = 0; mt < 2; mt++) {
        int r0 = mt * 16 + g;
#pragma unroll
        for (int half = 0; half < 2; half++) {
            int j = j0 + r0 + half * 8;
            if (j >= NQ) continue;
            float s = g_qinv[j] * taov;
#pragma unroll
            for (int nt = 0; nt < 4; nt++) {
                int c = wN * 32 + nt * 8 + 2 * t4;
                if (c < NCLS)     out[j * NCLS + c]     = C[mt][nt][half * 2 + 0] * s;
                if (c + 1 < NCLS) out[j * NCLS + c + 1] = C[mt][nt][half * 2 + 1] * s;
            }
        }
    }
}

// ---------------- 4) candidate selection (top-window) ----------------
__global__ void __launch_bounds__(256) cand_kernel() {
    __shared__ int scnt[8];
    int wq = threadIdx.x >> 5;
    int lane = threadIdx.x & 31;
    int j = blockIdx.x * 8 + wq;
    if (j >= NQ) return;
    const float* row = g_presim + j * NCLS;
    float v[4];
    float m = -INFINITY;
#pragma unroll
    for (int t = 0; t < 4; t++) {
        int c = lane + 32 * t;
        v[t] = (c < NCLS) ? row[c] : -INFINITY;
        m = fmaxf(m, v[t]);
    }
#pragma unroll
    for (int o = 16; o > 0; o >>= 1) m = fmaxf(m, __shfl_xor_sync(0xffffffffu, m, o));
    if (lane == 0) scnt[wq] = 0;
    __syncwarp();
#pragma unroll
    for (int t = 0; t < 4; t++) {
        int c = lane + 32 * t;
        if (c < NCLS && v[t] >= m - GAPT) {
            int p = atomicAdd(&scnt[wq], 1);
            if (p < MAXC) g_cand[j * MAXC + p] = c;
        }
    }
    __syncwarp();
    if (lane == 0) g_ncand[j] = min(scnt[wq], MAXC);
}

// ---------------- 5) exact refine: fp32 dots for candidates ----------------
__global__ void __launch_bounds__(128) refine_kernel(const float* __restrict__ x) {
    __shared__ float sred[32];
    __shared__ float sval[MAXC];
    int j = blockIdx.x;
    int nc = g_ncand[j];
    const float4* q = (const float4*)(x + (size_t)qrow(j) * D);
    for (int i = 0; i < nc; i++) {
        int c = g_cand[j * MAXC + i];
        const float4* p = (const float4*)(g_pn + (size_t)c * D);
        float s = 0.f;
#pragma unroll 4
        for (int t = threadIdx.x; t < D / 4; t += 128) {
            float4 a = q[t], b = p[t];
            s += a.x * b.x + a.y * b.y + a.z * b.z + a.w * b.w;
        }
        float tot = blk_sum(s, sred);
        if (threadIdx.x == 0) sval[i] = tot;
    }
    __syncthreads();
    if (threadIdx.x == 0) {
        float best = -INFINITY;
        int bi = 0x7fffffff;
        for (int i = 0; i < nc; i++) {
            float v = sval[i];
            int c = g_cand[j * MAXC + i];
            if (v > best || (v == best && c < bi)) { best = v; bi = c; }
        }
        g_label[j] = bi;
        g_win[j] = best * g_qinv[j];
    }
}

// ---------------- 6) softmax over assigned queries + adapted proto ----------------
#define MAXA 1024
__global__ void __launch_bounds__(256) adapt_kernel(const float* __restrict__ x) {
    __shared__ int   s_off[MAXA];
    __shared__ float s_w[MAXA];
    __shared__ float sred[32];
    __shared__ int   s_counts[257];

    int c = blockIdx.x, tid = threadIdx.x;

    const int chunk = (NQ + 255) / 256;
    int jlo = tid * chunk, jhi = min(NQ, jlo + chunk);
    int cnt = 0;
    for (int j = jlo; j < jhi; j++) cnt += (g_label[j] == c);
    s_counts[tid] = cnt;
    __syncthreads();
    if (tid == 0) {
        int run = 0;
        for (int i = 0; i < 256; i++) { int v = s_counts[i]; s_counts[i] = run; run += v; }
        s_counts[256] = run;
    }
    __syncthreads();
    int pos = s_counts[tid];
    for (int j = jlo; j < jhi; j++)
        if (g_label[j] == c) { if (pos < MAXA) s_off[pos] = j; pos++; }
    int total = min(s_counts[256], MAXA);
    __syncthreads();

    float m = g_self[c];
    for (int t = tid; t < total; t += 256) m = fmaxf(m, g_win[s_off[t]]);
    m = blk_max(m, sred);

    float se = 0.f;
    for (int t = tid; t < total; t += 256) {
        float e = expf(g_win[s_off[t]] - m);
        s_w[t] = e;
        se += e;
    }
    float eself = expf(g_self[c] - m);
    float Z = blk_sum(se, sred) + eself;
    float invZ = 1.f / Z;
    float wself = eself * invZ;
    for (int t = tid; t < total; t += 256) {
        s_w[t] *= invZ;
        s_off[t] = qrow(s_off[t]) * D;
    }
    __syncthreads();

    float accv[16];
#pragma unroll
    for (int s = 0; s < 16; s++) accv[s] = 0.f;
    for (int t = 0; t < total; t++) {
        float w = s_w[t];
        const float4* q4 = (const float4*)(x + s_off[t] + tid * 16);
#pragma unroll
        for (int v = 0; v < 4; v++) {
            float4 qv = q4[v];
            accv[v * 4 + 0] += w * qv.x;
            accv[v * 4 + 1] += w * qv.y;
            accv[v * 4 + 2] += w * qv.z;
            accv[v * 4 + 3] += w * qv.w;
        }
    }
    const float* pr = g_proto + (size_t)c * D + tid * 16;
    float ss = 0.f;
#pragma unroll
    for (int s = 0; s < 16; s++) {
        accv[s] += wself * pr[s];
        ss += accv[s] * accv[s];
    }
    float tot = blk_sum(ss, sred);
    float inv = 1.f / fmaxf(sqrtf(tot), EPSC);
    float* an = g_anh + (size_t)c * D + tid * 16;
#pragma unroll
    for (int s = 0; s < 16; s++) an[s] = f2tff(accv[s] * inv);
}

// ---------------- launch ----------------
extern "C" void kernel_launch(void* const* d_in, const int* in_sizes, int n_in,
                              void* d_out, int out_size) {
    const float* x   = (const float*)d_in[0];
    const float* tao = (const float*)d_in[1];
    float* out = (float*)d_out;

    float *presim, *xt, *pnh, *anh;
    cudaGetSymbolAddress((void**)&presim, g_presim);
    cudaGetSymbolAddress((void**)&xt,  g_xt);
    cudaGetSymbolAddress((void**)&pnh, g_pnh);
    cudaGetSymbolAddress((void**)&anh, g_anh);

    const int smem = 2 * (BM * APAD + BN * APAD) * 4;   // 46080 B
    const int nblk = (NQ + BM - 1) / BM;                // 235

    proto_kernel<<<NCLS, 256>>>(x);
    pack_kernel<<<NQ, 128>>>(x);
    mma_gemm<0><<<nblk, 128, smem>>>(xt, pnh, tao, presim);
    cand_kernel<<<(NQ + 7) / 8, 256>>>();
    refine_kernel<<<NQ, 128>>>(x);
    adapt_kernel<<<NCLS, 256>>>(x);
    mma_gemm<1><<<nblk, 128, smem>>>(xt, anh, tao, out);
}

// round 4
// speedup vs baseline: 5.0320x; 1.2463x over previous
#include <cuda_runtime.h>
#include <math.h>

#define D 4096
#define NCLS 100
#define KSUP 5
#define QPER 75
#define ROWSPC 80
#define NQ 7500
#define EPSC 1e-8f
#define GAPT_RAW 0.02f
#define MAXC 8
#define MAXA 1024

// ---------------- scratch ----------------
__device__ float g_proto[NCLS * D];
__device__ float g_pn[NCLS * D];        // exact fp32 normalized protos (refine)
__device__ float g_pnh[NCLS * D];       // RNA tf32 pn (gemm B)
__device__ float g_anh[NCLS * D];       // RNA tf32 adapted protos (gemm B)
__device__ float g_acc[NCLS * D];       // unnormalized adapted protos
__device__ float g_self[NCLS];
__device__ float g_qinv[NQ];
__device__ float g_presim[NQ * NCLS];   // RAW dots (unscaled)
__device__ float g_win[NQ];             // exact winner sim (scaled)
__device__ int   g_label[NQ];
__device__ int   g_cand[NQ * MAXC];
__device__ int   g_ncand[NQ];
__device__ float g_w[NCLS * MAXA];      // softmax weights per class
__device__ int   g_joff[NCLS * MAXA];   // row offsets (elements) per class
__device__ int   g_cnt[NCLS];
__device__ float g_wself[NCLS];
__device__ float g_nrmp[NCLS * 4];      // per-chunk sumsq partials

__device__ __forceinline__ int qrow(int j) {
    return (j / QPER) * ROWSPC + KSUP + (j % QPER);
}

__device__ __forceinline__ float f2tff(float f) {
    unsigned u;
    asm("cvt.rna.tf32.f32 %0, %1;" : "=r"(u) : "f"(f));
    return __uint_as_float(u);
}

// ---------------- block reductions ----------------
__device__ __forceinline__ float blk_sum(float v, float* sred) {
    int lane = threadIdx.x & 31, w = threadIdx.x >> 5;
#pragma unroll
    for (int o = 16; o > 0; o >>= 1) v += __shfl_down_sync(0xffffffffu, v, o);
    __syncthreads();
    if (lane == 0) sred[w] = v;
    __syncthreads();
    if (w == 0) {
        v = (lane < ((int)blockDim.x >> 5)) ? sred[lane] : 0.f;
#pragma unroll
        for (int o = 16; o > 0; o >>= 1) v += __shfl_down_sync(0xffffffffu, v, o);
        if (lane == 0) sred[0] = v;
    }
    __syncthreads();
    return sred[0];
}

__device__ __forceinline__ float blk_max(float v, float* sred) {
    int lane = threadIdx.x & 31, w = threadIdx.x >> 5;
#pragma unroll
    for (int o = 16; o > 0; o >>= 1) v = fmaxf(v, __shfl_down_sync(0xffffffffu, v, o));
    __syncthreads();
    if (lane == 0) sred[w] = v;
    __syncthreads();
    if (w == 0) {
        v = (lane < ((int)blockDim.x >> 5)) ? sred[lane] : -INFINITY;
#pragma unroll
        for (int o = 16; o > 0; o >>= 1) v = fmaxf(v, __shfl_down_sync(0xffffffffu, v, o));
        if (lane == 0) sred[0] = v;
    }
    __syncthreads();
    return sred[0];
}

// ---------------- 1) prototypes ----------------
__global__ void __launch_bounds__(256) proto_kernel(const float* __restrict__ x) {
    __shared__ float sred[32];
    int c = blockIdx.x;
    const float* sup = x + (size_t)c * ROWSPC * D;
    float ss = 0.f;
    for (int i = threadIdx.x; i < D; i += 256) {
        float s = (sup[i] + sup[D + i] + sup[2 * D + i] + sup[3 * D + i] + sup[4 * D + i]) * 0.2f;
        g_proto[c * D + i] = s;
        ss += s * s;
    }
    float tot = blk_sum(ss, sred);
    float inv = 1.f / fmaxf(sqrtf(tot), EPSC);
    float ss2 = 0.f;
    for (int i = threadIdx.x; i < D; i += 256) {
        float p = g_proto[c * D + i] * inv;
        g_pn[c * D + i] = p;
        g_pnh[c * D + i] = f2tff(p);
        ss2 += p * p;
    }
    float t2 = blk_sum(ss2, sred);
    if (threadIdx.x == 0) g_self[c] = t2;
}

// ---------------- 2)/7) tf32 mma GEMM (A = raw x rows, hw truncation) ----------------
// FIN=0: out[j,c] = raw dot      FIN=1: out[j,c] = dot * qinv[j] * tao
#define BM 32
#define BN 128
#define BK 32
#define APAD 36
#define NIT (D / BK)

#define CPA16(dst, src, sz) \
    asm volatile("cp.async.cg.shared.global [%0], [%1], 16, %2;\n" :: "r"(dst), "l"(src), "r"(sz))

__device__ __forceinline__ void mma_tf32(float c[4], const unsigned a[4], const unsigned b[2]) {
    asm volatile(
        "mma.sync.aligned.m16n8k8.row.col.f32.tf32.tf32.f32 "
        "{%0,%1,%2,%3}, {%4,%5,%6,%7}, {%8,%9}, {%0,%1,%2,%3};\n"
        : "+f"(c[0]), "+f"(c[1]), "+f"(c[2]), "+f"(c[3])
        : "r"(a[0]), "r"(a[1]), "r"(a[2]), "r"(a[3]), "r"(b[0]), "r"(b[1]));
}

template <int FIN>
__global__ void __launch_bounds__(128, 4) mma_gemm(const float* __restrict__ x,
                                                   const float* __restrict__ B,
                                                   const float* __restrict__ taop,
                                                   float* __restrict__ out) {
    extern __shared__ float sm[];
    constexpr int SA = BM * APAD;
    constexpr int SB = BN * APAD;
    constexpr int SS = SA + SB;

    const int tid = threadIdx.x;
    const int lane = tid & 31;
    const int wN = tid >> 5;
    const int g = lane >> 2;
    const int t4 = lane & 3;
    const int j0 = blockIdx.x * BM;

    float C[2][4][4];
#pragma unroll
    for (int mt = 0; mt < 2; mt++)
#pragma unroll
        for (int nt = 0; nt < 4; nt++)
#pragma unroll
            for (int r = 0; r < 4; r++) C[mt][nt][r] = 0.f;

    const unsigned smbase = (unsigned)__cvta_generic_to_shared(sm);

    auto load_tile = [&](int stg, int k0) {
        unsigned abase = smbase + stg * SS * 4;
#pragma unroll
        for (int i = 0; i < 2; i++) {
            int idx = tid + i * 128;
            int row = idx >> 3, seg = idx & 7;
            int j = j0 + row;
            const float* src = x + (size_t)qrow(j < NQ ? j : NQ - 1) * D + k0 + seg * 4;
            unsigned dst = abase + (row * APAD + seg * 4) * 4;
            CPA16(dst, src, (j < NQ) ? 16 : 0);
        }
        unsigned bbase = abase + SA * 4;
#pragma unroll
        for (int i = 0; i < 8; i++) {
            int idx = tid + i * 128;
            int n = idx >> 3, seg = idx & 7;
            const float* src = B + (size_t)(n < NCLS ? n : NCLS - 1) * D + k0 + seg * 4;
            unsigned dst = bbase + (n * APAD + seg * 4) * 4;
            CPA16(dst, src, (n < NCLS) ? 16 : 0);
        }
        asm volatile("cp.async.commit_group;\n");
    };

    load_tile(0, 0);

    for (int it = 0; it < NIT; it++) {
        asm volatile("cp.async.wait_group 0;\n");
        __syncthreads();
        if (it + 1 < NIT) load_tile((it + 1) & 1, (it + 1) * BK);

        const float* As = sm + (it & 1) * SS;
        const float* Bs = As + SA;

#pragma unroll
        for (int step = 0; step < 4; step++) {
            const int k = step * 8 + t4;
            unsigned a[2][4];
#pragma unroll
            for (int mt = 0; mt < 2; mt++) {
                int r0 = mt * 16 + g;
                a[mt][0] = __float_as_uint(As[r0 * APAD + k]);
                a[mt][1] = __float_as_uint(As[(r0 + 8) * APAD + k]);
                a[mt][2] = __float_as_uint(As[r0 * APAD + k + 4]);
                a[mt][3] = __float_as_uint(As[(r0 + 8) * APAD + k + 4]);
            }
            unsigned b[4][2];
#pragma unroll
            for (int nt = 0; nt < 4; nt++) {
                int n0 = wN * 32 + nt * 8 + g;
                b[nt][0] = __float_as_uint(Bs[n0 * APAD + k]);
                b[nt][1] = __float_as_uint(Bs[n0 * APAD + k + 4]);
            }
#pragma unroll
            for (int mt = 0; mt < 2; mt++)
#pragma unroll
                for (int nt = 0; nt < 4; nt++)
                    mma_tf32(C[mt][nt], a[mt], b[nt]);
        }
        __syncthreads();
    }

    const float taov = FIN ? taop[0] : 1.f;
#pragma unroll
    for (int mt = 0; mt < 2; mt++) {
        int r0 = mt * 16 + g;
#pragma unroll
        for (int half = 0; half < 2; half++) {
            int j = j0 + r0 + half * 8;
            if (j >= NQ) continue;
            float s = FIN ? (g_qinv[j] * taov) : 1.f;
#pragma unroll
            for (int nt = 0; nt < 4; nt++) {
                int c = wN * 32 + nt * 8 + 2 * t4;
                if (c < NCLS)     out[j * NCLS + c]     = C[mt][nt][half * 2 + 0] * s;
                if (c + 1 < NCLS) out[j * NCLS + c + 1] = C[mt][nt][half * 2 + 1] * s;
            }
        }
    }
}

// ---------------- 3) candidate selection on raw dots ----------------
__global__ void __launch_bounds__(256) cand_kernel() {
    __shared__ int scnt[8];
    int wq = threadIdx.x >> 5;
    int lane = threadIdx.x & 31;
    int j = blockIdx.x * 8 + wq;
    if (j >= NQ) return;
    const float* row = g_presim + j * NCLS;
    float v[4];
    float m = -INFINITY;
#pragma unroll
    for (int t = 0; t < 4; t++) {
        int c = lane + 32 * t;
        v[t] = (c < NCLS) ? row[c] : -INFINITY;
        m = fmaxf(m, v[t]);
    }
#pragma unroll
    for (int o = 16; o > 0; o >>= 1) m = fmaxf(m, __shfl_xor_sync(0xffffffffu, m, o));
    if (lane == 0) scnt[wq] = 0;
    __syncwarp();
#pragma unroll
    for (int t = 0; t < 4; t++) {
        int c = lane + 32 * t;
        if (c < NCLS && v[t] >= m - GAPT_RAW) {
            int p = atomicAdd(&scnt[wq], 1);
            if (p < MAXC) g_cand[j * MAXC + p] = c;
        }
    }
    __syncwarp();
    if (lane == 0) g_ncand[j] = min(scnt[wq], MAXC);
}

// ---------------- 4) exact refine (warp per query) + qinv ----------------
__global__ void __launch_bounds__(256) refine_kernel(const float* __restrict__ x) {
    int wq = threadIdx.x >> 5;
    int lane = threadIdx.x & 31;
    int j = blockIdx.x * 8 + wq;
    if (j >= NQ) return;
    int nc = g_ncand[j];
    const float4* q = (const float4*)(x + (size_t)qrow(j) * D);

    float best = -INFINITY;
    int bi = 0x7fffffff;
    float qq = 0.f;

    for (int base = 0; base < nc; base += 2) {
        int c0 = g_cand[j * MAXC + base];
        bool two = (base + 1 < nc);
        int c1 = two ? g_cand[j * MAXC + base + 1] : c0;
        const float4* p0 = (const float4*)(g_pn + (size_t)c0 * D);
        const float4* p1 = (const float4*)(g_pn + (size_t)c1 * D);
        float d0 = 0.f, d1 = 0.f;
#pragma unroll 4
        for (int i = lane; i < D / 4; i += 32) {
            float4 a = q[i];
            float4 b0 = p0[i];
            d0 += a.x * b0.x + a.y * b0.y + a.z * b0.z + a.w * b0.w;
            if (two) {
                float4 b1 = p1[i];
                d1 += a.x * b1.x + a.y * b1.y + a.z * b1.z + a.w * b1.w;
            }
            if (base == 0) qq += a.x * a.x + a.y * a.y + a.z * a.z + a.w * a.w;
        }
#pragma unroll
        for (int o = 16; o > 0; o >>= 1) {
            d0 += __shfl_xor_sync(0xffffffffu, d0, o);
            d1 += __shfl_xor_sync(0xffffffffu, d1, o);
            if (base == 0) qq += __shfl_xor_sync(0xffffffffu, qq, o);
        }
        if (d0 > best || (d0 == best && c0 < bi)) { best = d0; bi = c0; }
        if (two && (d1 > best || (d1 == best && c1 < bi))) { best = d1; bi = c1; }
    }
    if (lane == 0) {
        float qinv = 1.f / fmaxf(sqrtf(qq), EPSC);
        g_label[j] = bi;
        g_qinv[j] = qinv;
        g_win[j] = best * qinv;
    }
}

// ---------------- 5a) softmax weights per class ----------------
__global__ void __launch_bounds__(256) weights_kernel() {
    __shared__ int   s_off[MAXA];
    __shared__ float sred[32];
    __shared__ int   s_counts[257];

    int c = blockIdx.x, tid = threadIdx.x;

    const int chunk = (NQ + 255) / 256;
    int jlo = tid * chunk, jhi = min(NQ, jlo + chunk);
    int cnt = 0;
    for (int j = jlo; j < jhi; j++) cnt += (g_label[j] == c);
    s_counts[tid] = cnt;
    __syncthreads();
    if (tid == 0) {
        int run = 0;
        for (int i = 0; i < 256; i++) { int v = s_counts[i]; s_counts[i] = run; run += v; }
        s_counts[256] = run;
    }
    __syncthreads();
    int pos = s_counts[tid];
    for (int j = jlo; j < jhi; j++)
        if (g_label[j] == c) { if (pos < MAXA) s_off[pos] = j; pos++; }
    int total = min(s_counts[256], MAXA);
    __syncthreads();

    float m = g_self[c];
    for (int t = tid; t < total; t += 256) m = fmaxf(m, g_win[s_off[t]]);
    m = blk_max(m, sred);

    float se = 0.f;
    float ebuf[(MAXA + 255) / 256];
    for (int t = tid, r = 0; t < total; t += 256, r++) {
        float e = expf(g_win[s_off[t]] - m);
        ebuf[r] = e;
        se += e;
    }
    float eself = expf(g_self[c] - m);
    float Z = blk_sum(se, sred) + eself;
    float invZ = 1.f / Z;
    for (int t = tid, r = 0; t < total; t += 256, r++) {
        g_w[c * MAXA + t] = ebuf[r] * invZ;
        g_joff[c * MAXA + t] = qrow(s_off[t]) * D;
    }
    if (tid == 0) {
        g_cnt[c] = total;
        g_wself[c] = eself * invZ;
    }
}

// ---------------- 5b) weighted sum chunks + norm partials ----------------
__global__ void __launch_bounds__(256) wsum_kernel(const float* __restrict__ x) {
    __shared__ float sred[32];
    int ch = blockIdx.x;            // 0..3 (1024-dim chunk)
    int c  = blockIdx.y;
    int tid = threadIdx.x;
    int dim = ch * 1024 + tid * 4;
    int total = g_cnt[c];

    float4 acc = make_float4(0.f, 0.f, 0.f, 0.f);
    for (int t = 0; t < total; t++) {
        float w = g_w[c * MAXA + t];
        float4 v = *(const float4*)(x + g_joff[c * MAXA + t] + dim);
        acc.x += w * v.x; acc.y += w * v.y; acc.z += w * v.z; acc.w += w * v.w;
    }
    float wself = g_wself[c];
    float4 pr = *(const float4*)(g_proto + (size_t)c * D + dim);
    acc.x += wself * pr.x; acc.y += wself * pr.y; acc.z += wself * pr.z; acc.w += wself * pr.w;
    *(float4*)(g_acc + (size_t)c * D + dim) = acc;
    float ss = acc.x * acc.x + acc.y * acc.y + acc.z * acc.z + acc.w * acc.w;
    float tot = blk_sum(ss, sred);
    if (tid == 0) g_nrmp[c * 4 + ch] = tot;
}

// ---------------- 5c) normalize + RNA round ----------------
__global__ void __launch_bounds__(256) norm_kernel() {
    int c = blockIdx.x;
    float nrm = g_nrmp[c * 4 + 0] + g_nrmp[c * 4 + 1] + g_nrmp[c * 4 + 2] + g_nrmp[c * 4 + 3];
    float inv = 1.f / fmaxf(sqrtf(nrm), EPSC);
    for (int i = threadIdx.x; i < D; i += 256)
        g_anh[(size_t)c * D + i] = f2tff(g_acc[(size_t)c * D + i] * inv);
}

// ---------------- launch ----------------
extern "C" void kernel_launch(void* const* d_in, const int* in_sizes, int n_in,
                              void* d_out, int out_size) {
    const float* x   = (const float*)d_in[0];
    const float* tao = (const float*)d_in[1];
    float* out = (float*)d_out;

    float *presim, *pnh, *anh;
    cudaGetSymbolAddress((void**)&presim, g_presim);
    cudaGetSymbolAddress((void**)&pnh, g_pnh);
    cudaGetSymbolAddress((void**)&anh, g_anh);

    const int smem = 2 * (BM * APAD + BN * APAD) * 4;   // 46080 B
    const int nblk = (NQ + BM - 1) / BM;                // 235

    proto_kernel<<<NCLS, 256>>>(x);
    mma_gemm<0><<<nblk, 128, smem>>>(x, pnh, tao, presim);
    cand_kernel<<<(NQ + 7) / 8, 256>>>();
    refine_kernel<<<(NQ + 7) / 8, 256>>>(x);
    weights_kernel<<<NCLS, 256>>>();
    wsum_kernel<<<dim3(4, NCLS), 256>>>(x);
    norm_kernel<<<NCLS, 256>>>();
    mma_gemm<1><<<nblk, 128, smem>>>(x, anh, tao, out);
}

// round 5
// speedup vs baseline: 5.4676x; 1.0866x over previous
#include <cuda_runtime.h>
#include <math.h>

#define D 4096
#define NCLS 100
#define KSUP 5
#define QPER 75
#define ROWSPC 80
#define NQ 7500
#define EPSC 1e-8f
#define GAPT_RAW 0.008f
#define MAXC 8
#define MAXA 1024

// ---------------- scratch ----------------
__device__ float g_proto[NCLS * D];
__device__ float g_pn[NCLS * D];        // exact fp32 normalized protos (refine)
__device__ float g_pnh[NCLS * D];       // RNA tf32 pn (gemm B)
__device__ float g_anh[NCLS * D];       // RNA tf32 adapted protos (gemm B)
__device__ float g_acc[NCLS * D];       // unnormalized adapted protos
__device__ float g_self[NCLS];
__device__ float g_qinv[NQ];
__device__ float g_presim[NQ * NCLS];   // RAW dots (unscaled)
__device__ float g_win[NQ];             // winner sim (scaled)
__device__ int   g_label[NQ];
__device__ int   g_cand[NQ * MAXC];
__device__ int   g_ncand[NQ];
__device__ int   g_work[NQ];
__device__ int   g_nwork;
__device__ float g_w[NCLS * MAXA];
__device__ int   g_joff[NCLS * MAXA];
__device__ int   g_cnt[NCLS];
__device__ float g_wself[NCLS];
__device__ float g_nrmp[NCLS * 4];

__device__ __forceinline__ int qrow(int j) {
    return (j / QPER) * ROWSPC + KSUP + (j % QPER);
}

__device__ __forceinline__ float f2tff(float f) {
    unsigned u;
    asm("cvt.rna.tf32.f32 %0, %1;" : "=r"(u) : "f"(f));
    return __uint_as_float(u);
}

// ---------------- block reductions ----------------
__device__ __forceinline__ float blk_sum(float v, float* sred) {
    int lane = threadIdx.x & 31, w = threadIdx.x >> 5;
#pragma unroll
    for (int o = 16; o > 0; o >>= 1) v += __shfl_down_sync(0xffffffffu, v, o);
    __syncthreads();
    if (lane == 0) sred[w] = v;
    __syncthreads();
    if (w == 0) {
        v = (lane < ((int)blockDim.x >> 5)) ? sred[lane] : 0.f;
#pragma unroll
        for (int o = 16; o > 0; o >>= 1) v += __shfl_down_sync(0xffffffffu, v, o);
        if (lane == 0) sred[0] = v;
    }
    __syncthreads();
    return sred[0];
}

__device__ __forceinline__ float blk_max(float v, float* sred) {
    int lane = threadIdx.x & 31, w = threadIdx.x >> 5;
#pragma unroll
    for (int o = 16; o > 0; o >>= 1) v = fmaxf(v, __shfl_down_sync(0xffffffffu, v, o));
    __syncthreads();
    if (lane == 0) sred[w] = v;
    __syncthreads();
    if (w == 0) {
        v = (lane < ((int)blockDim.x >> 5)) ? sred[lane] : -INFINITY;
#pragma unroll
        for (int o = 16; o > 0; o >>= 1) v = fmaxf(v, __shfl_down_sync(0xffffffffu, v, o));
        if (lane == 0) sred[0] = v;
    }
    __syncthreads();
    return sred[0];
}

// ---------------- 1) prototypes (+ reset worklist counter) ----------------
__global__ void __launch_bounds__(256) proto_kernel(const float* __restrict__ x) {
    __shared__ float sred[32];
    int c = blockIdx.x;
    if (c == 0 && threadIdx.x == 0) g_nwork = 0;
    const float* sup = x + (size_t)c * ROWSPC * D;
    float ss = 0.f;
    for (int i = threadIdx.x; i < D; i += 256) {
        float s = (sup[i] + sup[D + i] + sup[2 * D + i] + sup[3 * D + i] + sup[4 * D + i]) * 0.2f;
        g_proto[c * D + i] = s;
        ss += s * s;
    }
    float tot = blk_sum(ss, sred);
    float inv = 1.f / fmaxf(sqrtf(tot), EPSC);
    float ss2 = 0.f;
    for (int i = threadIdx.x; i < D; i += 256) {
        float p = g_proto[c * D + i] * inv;
        g_pn[c * D + i] = p;
        g_pnh[c * D + i] = f2tff(p);
        ss2 += p * p;
    }
    float t2 = blk_sum(ss2, sred);
    if (threadIdx.x == 0) g_self[c] = t2;
}

// ---------------- 2)/7) tf32 mma GEMM (A raw, hw truncation); FIN=0 also computes qinv ----------------
#define BM 32
#define BN 128
#define BK 32
#define APAD 36
#define NIT (D / BK)

#define CPA16(dst, src, sz) \
    asm volatile("cp.async.cg.shared.global [%0], [%1], 16, %2;\n" :: "r"(dst), "l"(src), "r"(sz))

__device__ __forceinline__ void mma_tf32(float c[4], const unsigned a[4], const unsigned b[2]) {
    asm volatile(
        "mma.sync.aligned.m16n8k8.row.col.f32.tf32.tf32.f32 "
        "{%0,%1,%2,%3}, {%4,%5,%6,%7}, {%8,%9}, {%0,%1,%2,%3};\n"
        : "+f"(c[0]), "+f"(c[1]), "+f"(c[2]), "+f"(c[3])
        : "r"(a[0]), "r"(a[1]), "r"(a[2]), "r"(a[3]), "r"(b[0]), "r"(b[1]));
}

template <int FIN>
__global__ void __launch_bounds__(128, 4) mma_gemm(const float* __restrict__ x,
                                                   const float* __restrict__ B,
                                                   const float* __restrict__ taop,
                                                   float* __restrict__ out) {
    extern __shared__ float sm[];
    constexpr int SA = BM * APAD;
    constexpr int SB = BN * APAD;
    constexpr int SS = SA + SB;

    const int tid = threadIdx.x;
    const int lane = tid & 31;
    const int wN = tid >> 5;
    const int g = lane >> 2;
    const int t4 = lane & 3;
    const int j0 = blockIdx.x * BM;

    float C[2][4][4];
#pragma unroll
    for (int mt = 0; mt < 2; mt++)
#pragma unroll
        for (int nt = 0; nt < 4; nt++)
#pragma unroll
            for (int r = 0; r < 4; r++) C[mt][nt][r] = 0.f;

    float qq = 0.f;   // exact per-row sumsq partial (rows tid>>2, col chunk tid&3)

    const unsigned smbase = (unsigned)__cvta_generic_to_shared(sm);

    auto load_tile = [&](int stg, int k0) {
        unsigned abase = smbase + stg * SS * 4;
#pragma unroll
        for (int i = 0; i < 2; i++) {
            int idx = tid + i * 128;
            int row = idx >> 3, seg = idx & 7;
            int j = j0 + row;
            const float* src = x + (size_t)qrow(j < NQ ? j : NQ - 1) * D + k0 + seg * 4;
            unsigned dst = abase + (row * APAD + seg * 4) * 4;
            CPA16(dst, src, (j < NQ) ? 16 : 0);
        }
        unsigned bbase = abase + SA * 4;
#pragma unroll
        for (int i = 0; i < 8; i++) {
            int idx = tid + i * 128;
            int n = idx >> 3, seg = idx & 7;
            const float* src = B + (size_t)(n < NCLS ? n : NCLS - 1) * D + k0 + seg * 4;
            unsigned dst = bbase + (n * APAD + seg * 4) * 4;
            CPA16(dst, src, (n < NCLS) ? 16 : 0);
        }
        asm volatile("cp.async.commit_group;\n");
    };

    load_tile(0, 0);

    for (int it = 0; it < NIT; it++) {
        asm volatile("cp.async.wait_group 0;\n");
        __syncthreads();
        if (it + 1 < NIT) load_tile((it + 1) & 1, (it + 1) * BK);

        const float* As = sm + (it & 1) * SS;
        const float* Bs = As + SA;

        if (!FIN) {
            const float* Ar = As + (tid >> 2) * APAD + (tid & 3) * 8;
#pragma unroll
            for (int i = 0; i < 8; i++) { float v = Ar[i]; qq += v * v; }
        }

#pragma unroll
        for (int step = 0; step < 4; step++) {
            const int k = step * 8 + t4;
            unsigned a[2][4];
#pragma unroll
            for (int mt = 0; mt < 2; mt++) {
                int r0 = mt * 16 + g;
                a[mt][0] = __float_as_uint(As[r0 * APAD + k]);
                a[mt][1] = __float_as_uint(As[(r0 + 8) * APAD + k]);
                a[mt][2] = __float_as_uint(As[r0 * APAD + k + 4]);
                a[mt][3] = __float_as_uint(As[(r0 + 8) * APAD + k + 4]);
            }
            unsigned b[4][2];
#pragma unroll
            for (int nt = 0; nt < 4; nt++) {
                int n0 = wN * 32 + nt * 8 + g;
                b[nt][0] = __float_as_uint(Bs[n0 * APAD + k]);
                b[nt][1] = __float_as_uint(Bs[n0 * APAD + k + 4]);
            }
#pragma unroll
            for (int mt = 0; mt < 2; mt++)
#pragma unroll
                for (int nt = 0; nt < 4; nt++)
                    mma_tf32(C[mt][nt], a[mt], b[nt]);
        }
        __syncthreads();
    }

    if (!FIN) {
        qq += __shfl_down_sync(0xffffffffu, qq, 1);
        qq += __shfl_down_sync(0xffffffffu, qq, 2);
        if ((tid & 3) == 0) {
            int j = j0 + (tid >> 2);
            if (j < NQ) g_qinv[j] = 1.f / fmaxf(sqrtf(qq), EPSC);
        }
    }

    const float taov = FIN ? taop[0] : 1.f;
#pragma unroll
    for (int mt = 0; mt < 2; mt++) {
        int r0 = mt * 16 + g;
#pragma unroll
        for (int half = 0; half < 2; half++) {
            int j = j0 + r0 + half * 8;
            if (j >= NQ) continue;
            float s = FIN ? (g_qinv[j] * taov) : 1.f;
#pragma unroll
            for (int nt = 0; nt < 4; nt++) {
                int c = wN * 32 + nt * 8 + 2 * t4;
                if (c < NCLS)     out[j * NCLS + c]     = C[mt][nt][half * 2 + 0] * s;
                if (c + 1 < NCLS) out[j * NCLS + c + 1] = C[mt][nt][half * 2 + 1] * s;
            }
        }
    }
}

// ---------------- 3) candidates; finalize easy queries, worklist hard ones ----------------
__global__ void __launch_bounds__(256) cand_kernel() {
    __shared__ int scnt[8];
    int wq = threadIdx.x >> 5;
    int lane = threadIdx.x & 31;
    int j = blockIdx.x * 8 + wq;
    if (j >= NQ) return;
    const float* row = g_presim + j * NCLS;
    float v[4];
    float m = -INFINITY;
#pragma unroll
    for (int t = 0; t < 4; t++) {
        int c = lane + 32 * t;
        v[t] = (c < NCLS) ? row[c] : -INFINITY;
        m = fmaxf(m, v[t]);
    }
#pragma unroll
    for (int o = 16; o > 0; o >>= 1) m = fmaxf(m, __shfl_xor_sync(0xffffffffu, m, o));
    if (lane == 0) scnt[wq] = 0;
    __syncwarp();
#pragma unroll
    for (int t = 0; t < 4; t++) {
        int c = lane + 32 * t;
        if (c < NCLS && v[t] >= m - GAPT_RAW) {
            int p = atomicAdd(&scnt[wq], 1);
            if (p < MAXC) g_cand[j * MAXC + p] = c;
        }
    }
    __syncwarp();
    if (lane == 0) {
        int nc = min(scnt[wq], MAXC);
        g_ncand[j] = nc;
        if (nc == 1) {
            int c = g_cand[j * MAXC];
            g_label[j] = c;
            g_win[j] = g_presim[j * NCLS + c] * g_qinv[j];
        } else {
            int p = atomicAdd(&g_nwork, 1);
            g_work[p] = j;
        }
    }
}

// ---------------- 4) exact refine for near-tie queries (persistent warps) ----------------
__global__ void __launch_bounds__(256) refine_kernel(const float* __restrict__ x) {
    int lane = threadIdx.x & 31;
    int wid = blockIdx.x * 8 + (threadIdx.x >> 5);
    const int nwarps = gridDim.x * 8;
    int nw = g_nwork;

    for (int t = wid; t < nw; t += nwarps) {
        int j = g_work[t];
        int nc = g_ncand[j];
        const float4* q = (const float4*)(x + (size_t)qrow(j) * D);
        float best = -INFINITY;
        int bi = 0x7fffffff;
        for (int base = 0; base < nc; base += 2) {
            int c0 = g_cand[j * MAXC + base];
            bool two = (base + 1 < nc);
            int c1 = two ? g_cand[j * MAXC + base + 1] : c0;
            const float4* p0 = (const float4*)(g_pn + (size_t)c0 * D);
            const float4* p1 = (const float4*)(g_pn + (size_t)c1 * D);
            float d0 = 0.f, d1 = 0.f;
#pragma unroll 4
            for (int i = lane; i < D / 4; i += 32) {
                float4 a = q[i];
                float4 b0 = p0[i];
                d0 += a.x * b0.x + a.y * b0.y + a.z * b0.z + a.w * b0.w;
                if (two) {
                    float4 b1 = p1[i];
                    d1 += a.x * b1.x + a.y * b1.y + a.z * b1.z + a.w * b1.w;
                }
            }
#pragma unroll
            for (int o = 16; o > 0; o >>= 1) {
                d0 += __shfl_xor_sync(0xffffffffu, d0, o);
                d1 += __shfl_xor_sync(0xffffffffu, d1, o);
            }
            if (d0 > best || (d0 == best && c0 < bi)) { best = d0; bi = c0; }
            if (two && (d1 > best || (d1 == best && c1 < bi))) { best = d1; bi = c1; }
        }
        if (lane == 0) {
            g_label[j] = bi;
            g_win[j] = best * g_qinv[j];
        }
    }
}

// ---------------- 5a) softmax weights per class ----------------
__global__ void __launch_bounds__(256) weights_kernel() {
    __shared__ int   s_off[MAXA];
    __shared__ float sred[32];
    __shared__ int   s_counts[257];

    int c = blockIdx.x, tid = threadIdx.x;

    const int chunk = (NQ + 255) / 256;
    int jlo = tid * chunk, jhi = min(NQ, jlo + chunk);
    int cnt = 0;
    for (int j = jlo; j < jhi; j++) cnt += (g_label[j] == c);
    s_counts[tid] = cnt;
    __syncthreads();
    if (tid == 0) {
        int run = 0;
        for (int i = 0; i < 256; i++) { int v = s_counts[i]; s_counts[i] = run; run += v; }
        s_counts[256] = run;
    }
    __syncthreads();
    int pos = s_counts[tid];
    for (int j = jlo; j < jhi; j++)
        if (g_label[j] == c) { if (pos < MAXA) s_off[pos] = j; pos++; }
    int total = min(s_counts[256], MAXA);
    __syncthreads();

    float m = g_self[c];
    for (int t = tid; t < total; t += 256) m = fmaxf(m, g_win[s_off[t]]);
    m = blk_max(m, sred);

    float se = 0.f;
    float ebuf[(MAXA + 255) / 256];
    for (int t = tid, r = 0; t < total; t += 256, r++) {
        float e = expf(g_win[s_off[t]] - m);
        ebuf[r] = e;
        se += e;
    }
    float eself = expf(g_self[c] - m);
    float Z = blk_sum(se, sred) + eself;
    float invZ = 1.f / Z;
    for (int t = tid, r = 0; t < total; t += 256, r++) {
        g_w[c * MAXA + t] = ebuf[r] * invZ;
        g_joff[c * MAXA + t] = qrow(s_off[t]) * D;
    }
    if (tid == 0) {
        g_cnt[c] = total;
        g_wself[c] = eself * invZ;
    }
}

// ---------------- 5b) weighted sum chunks + norm partials ----------------
__global__ void __launch_bounds__(256) wsum_kernel(const float* __restrict__ x) {
    __shared__ float sred[32];
    __shared__ float sw[MAXA];
    __shared__ int   soff[MAXA];
    int ch = blockIdx.x;
    int c  = blockIdx.y;
    int tid = threadIdx.x;
    int dim = ch * 1024 + tid * 4;
    int total = g_cnt[c];

    for (int i = tid; i < total; i += 256) {
        sw[i] = g_w[c * MAXA + i];
        soff[i] = g_joff[c * MAXA + i];
    }
    __syncthreads();

    float4 a0 = make_float4(0.f, 0.f, 0.f, 0.f);
    float4 a1 = make_float4(0.f, 0.f, 0.f, 0.f);
    float4 a2 = make_float4(0.f, 0.f, 0.f, 0.f);
    float4 a3 = make_float4(0.f, 0.f, 0.f, 0.f);
    int t = 0;
    for (; t + 4 <= total; t += 4) {
        float w0 = sw[t], w1 = sw[t + 1], w2 = sw[t + 2], w3 = sw[t + 3];
        float4 v0 = *(const float4*)(x + soff[t] + dim);
        float4 v1 = *(const float4*)(x + soff[t + 1] + dim);
        float4 v2 = *(const float4*)(x + soff[t + 2] + dim);
        float4 v3 = *(const float4*)(x + soff[t + 3] + dim);
        a0.x += w0 * v0.x; a0.y += w0 * v0.y; a0.z += w0 * v0.z; a0.w += w0 * v0.w;
        a1.x += w1 * v1.x; a1.y += w1 * v1.y; a1.z += w1 * v1.z; a1.w += w1 * v1.w;
        a2.x += w2 * v2.x; a2.y += w2 * v2.y; a2.z += w2 * v2.z; a2.w += w2 * v2.w;
        a3.x += w3 * v3.x; a3.y += w3 * v3.y; a3.z += w3 * v3.z; a3.w += w3 * v3.w;
    }
    for (; t < total; t++) {
        float w = sw[t];
        float4 v = *(const float4*)(x + soff[t] + dim);
        a0.x += w * v.x; a0.y += w * v.y; a0.z += w * v.z; a0.w += w * v.w;
    }
    float wself = g_wself[c];
    float4 pr = *(const float4*)(g_proto + (size_t)c * D + dim);
    float4 acc;
    acc.x = a0.x + a1.x + a2.x + a3.x + wself * pr.x;
    acc.y = a0.y + a1.y + a2.y + a3.y + wself * pr.y;
    acc.z = a0.z + a1.z + a2.z + a3.z + wself * pr.z;
    acc.w = a0.w + a1.w + a2.w + a3.w + wself * pr.w;
    *(float4*)(g_acc + (size_t)c * D + dim) = acc;
    float ss = acc.x * acc.x + acc.y * acc.y + acc.z * acc.z + acc.w * acc.w;
    float tot = blk_sum(ss, sred);
    if (tid == 0) g_nrmp[c * 4 + ch] = tot;
}

// ---------------- 5c) normalize + RNA round ----------------
__global__ void __launch_bounds__(256) norm_kernel() {
    int c = blockIdx.x;
    float nrm = g_nrmp[c * 4 + 0] + g_nrmp[c * 4 + 1] + g_nrmp[c * 4 + 2] + g_nrmp[c * 4 + 3];
    float inv = 1.f / fmaxf(sqrtf(nrm), EPSC);
    for (int i = threadIdx.x; i < D; i += 256)
        g_anh[(size_t)c * D + i] = f2tff(g_acc[(size_t)c * D + i] * inv);
}

// ---------------- launch ----------------
extern "C" void kernel_launch(void* const* d_in, const int* in_sizes, int n_in,
                              void* d_out, int out_size) {
    const float* x   = (const float*)d_in[0];
    const float* tao = (const float*)d_in[1];
    float* out = (float*)d_out;

    float *presim, *pnh, *anh;
    cudaGetSymbolAddress((void**)&presim, g_presim);
    cudaGetSymbolAddress((void**)&pnh, g_pnh);
    cudaGetSymbolAddress((void**)&anh, g_anh);

    const int smem = 2 * (BM * APAD + BN * APAD) * 4;   // 46080 B
    const int nblk = (NQ + BM - 1) / BM;                // 235

    proto_kernel<<<NCLS, 256>>>(x);
    mma_gemm<0><<<nblk, 128, smem>>>(x, pnh, tao, presim);
    cand_kernel<<<(NQ + 7) / 8, 256>>>();
    refine_kernel<<<59, 256>>>(x);
    weights_kernel<<<NCLS, 256>>>();
    wsum_kernel<<<dim3(4, NCLS), 256>>>(x);
    norm_kernel<<<NCLS, 256>>>();
    mma_gemm<1><<<nblk, 128, smem>>>(x, anh, tao, out);
}

// round 6
// speedup vs baseline: 5.9027x; 1.0796x over previous
#include <cuda_runtime.h>
#include <math.h>

#define D 4096
#define NCLS 100
#define KSUP 5
#define QPER 75
#define ROWSPC 80
#define NQ 7500
#define EPSC 1e-8f
#define GAPT_RAW 0.008f
#define MAXC 8
#define MAXA 1024

// ---------------- scratch ----------------
__device__ float g_proto[NCLS * D];
__device__ float g_pn[NCLS * D];        // exact fp32 normalized protos (refine)
__device__ float g_pnh[NCLS * D];       // RNA tf32 pn (gemm B)
__device__ float g_anh[NCLS * D];       // RNA tf32 adapted protos (gemm B)
__device__ float g_self[NCLS];
__device__ float g_qinv[NQ];
__device__ float g_win[NQ];
__device__ int   g_label[NQ];
__device__ int   g_cand[NQ * MAXC];
__device__ int   g_ncand[NQ];
__device__ int   g_work[NQ];
__device__ int   g_nwork;
__device__ float g_w[NCLS * MAXA];
__device__ int   g_joff[NCLS * MAXA];
__device__ int   g_cnt[NCLS];
__device__ float g_wself[NCLS];

__device__ __forceinline__ int qrow(int j) {
    return (j / QPER) * ROWSPC + KSUP + (j % QPER);
}

__device__ __forceinline__ float f2tff(float f) {
    unsigned u;
    asm("cvt.rna.tf32.f32 %0, %1;" : "=r"(u) : "f"(f));
    return __uint_as_float(u);
}

// ---------------- block reductions (any blockDim multiple of 32, <=1024) ----------------
__device__ __forceinline__ float blk_sum(float v, float* sred) {
    int lane = threadIdx.x & 31, w = threadIdx.x >> 5;
#pragma unroll
    for (int o = 16; o > 0; o >>= 1) v += __shfl_down_sync(0xffffffffu, v, o);
    __syncthreads();
    if (lane == 0) sred[w] = v;
    __syncthreads();
    if (w == 0) {
        v = (lane < ((int)blockDim.x >> 5)) ? sred[lane] : 0.f;
#pragma unroll
        for (int o = 16; o > 0; o >>= 1) v += __shfl_down_sync(0xffffffffu, v, o);
        if (lane == 0) sred[0] = v;
    }
    __syncthreads();
    return sred[0];
}

__device__ __forceinline__ float blk_max(float v, float* sred) {
    int lane = threadIdx.x & 31, w = threadIdx.x >> 5;
#pragma unroll
    for (int o = 16; o > 0; o >>= 1) v = fmaxf(v, __shfl_down_sync(0xffffffffu, v, o));
    __syncthreads();
    if (lane == 0) sred[w] = v;
    __syncthreads();
    if (w == 0) {
        v = (lane < ((int)blockDim.x >> 5)) ? sred[lane] : -INFINITY;
#pragma unroll
        for (int o = 16; o > 0; o >>= 1) v = fmaxf(v, __shfl_down_sync(0xffffffffu, v, o));
        if (lane == 0) sred[0] = v;
    }
    __syncthreads();
    return sred[0];
}

// ---------------- 1) prototypes: float4, single pass in registers ----------------
__global__ void __launch_bounds__(1024) proto_kernel(const float* __restrict__ x) {
    __shared__ float sred[32];
    int c = blockIdx.x;
    int i = threadIdx.x;          // 1024 threads == D/4 slots
    if (c == 0 && i == 0) g_nwork = 0;
    const float4* sup = (const float4*)(x + (size_t)c * ROWSPC * D);
    const int DQ = D / 4;
    float4 v0 = sup[i];
    float4 v1 = sup[DQ + i];
    float4 v2 = sup[2 * DQ + i];
    float4 v3 = sup[3 * DQ + i];
    float4 v4 = sup[4 * DQ + i];
    float4 s;
    s.x = (v0.x + v1.x + v2.x + v3.x + v4.x) * 0.2f;
    s.y = (v0.y + v1.y + v2.y + v3.y + v4.y) * 0.2f;
    s.z = (v0.z + v1.z + v2.z + v3.z + v4.z) * 0.2f;
    s.w = (v0.w + v1.w + v2.w + v3.w + v4.w) * 0.2f;
    ((float4*)(g_proto + (size_t)c * D))[i] = s;
    float ss = s.x * s.x + s.y * s.y + s.z * s.z + s.w * s.w;
    float tot = blk_sum(ss, sred);
    float inv = 1.f / fmaxf(sqrtf(tot), EPSC);
    float4 p;
    p.x = s.x * inv; p.y = s.y * inv; p.z = s.z * inv; p.w = s.w * inv;
    ((float4*)(g_pn + (size_t)c * D))[i] = p;
    float4 ph;
    ph.x = f2tff(p.x); ph.y = f2tff(p.y); ph.z = f2tff(p.z); ph.w = f2tff(p.w);
    ((float4*)(g_pnh + (size_t)c * D))[i] = ph;
    float ss2 = p.x * p.x + p.y * p.y + p.z * p.z + p.w * p.w;
    float t2 = blk_sum(ss2, sred);
    if (i == 0) g_self[c] = t2;
}

// ---------------- 2)/6) tf32 mma GEMM, N pruned to 104, fused epilogues ----------------
#define BM 32
#define BNROWS 104           // B rows staged (classes, padded to x8)
#define BK 32
#define APAD 36
#define NIT (D / BK)
#define PSTRIDE 136          // presim smem row stride (floats)

#define CPA16(dst, src, sz) \
    asm volatile("cp.async.cg.shared.global [%0], [%1], 16, %2;\n" :: "r"(dst), "l"(src), "r"(sz))

__device__ __forceinline__ void mma_tf32(float c[4], const unsigned a[4], const unsigned b[2]) {
    asm volatile(
        "mma.sync.aligned.m16n8k8.row.col.f32.tf32.tf32.f32 "
        "{%0,%1,%2,%3}, {%4,%5,%6,%7}, {%8,%9}, {%0,%1,%2,%3};\n"
        : "+f"(c[0]), "+f"(c[1]), "+f"(c[2]), "+f"(c[3])
        : "r"(a[0]), "r"(a[1]), "r"(a[2]), "r"(a[3]), "r"(b[0]), "r"(b[1]));
}

template <int FIN>
__global__ void __launch_bounds__(128, 4) mma_gemm(const float* __restrict__ x,
                                                   const float* __restrict__ B,
                                                   const float* __restrict__ taop,
                                                   float* __restrict__ out) {
    extern __shared__ float sm[];
    __shared__ float sq[BM];
    constexpr int SA = BM * APAD;          // 1152
    constexpr int SB = BNROWS * APAD;      // 3744
    constexpr int SS = SA + SB;            // 4896 floats per stage

    const int tid = threadIdx.x;
    const int lane = tid & 31;
    const int wN = tid >> 5;               // 0..3, covers n = wN*32..+32 (warp3 pruned)
    const int g = lane >> 2;
    const int t4 = lane & 3;
    const int j0 = blockIdx.x * BM;

    float C[2][4][4];
#pragma unroll
    for (int mt = 0; mt < 2; mt++)
#pragma unroll
        for (int nt = 0; nt < 4; nt++)
#pragma unroll
            for (int r = 0; r < 4; r++) C[mt][nt][r] = 0.f;

    float qq = 0.f;

    const unsigned smbase = (unsigned)__cvta_generic_to_shared(sm);

    auto load_tile = [&](int stg, int k0) {
        unsigned abase = smbase + stg * SS * 4;
#pragma unroll
        for (int i = 0; i < 2; i++) {
            int idx = tid + i * 128;
            int row = idx >> 3, seg = idx & 7;
            int j = j0 + row;
            const float* src = x + (size_t)qrow(j < NQ ? j : NQ - 1) * D + k0 + seg * 4;
            unsigned dst = abase + (row * APAD + seg * 4) * 4;
            CPA16(dst, src, (j < NQ) ? 16 : 0);
        }
        unsigned bbase = abase + SA * 4;
#pragma unroll
        for (int i = 0; i < 7; i++) {                  // 104 rows * 8 slots = 832
            int idx = tid + i * 128;
            if (idx < BNROWS * 8) {
                int n = idx >> 3, seg = idx & 7;
                const float* src = B + (size_t)(n < NCLS ? n : NCLS - 1) * D + k0 + seg * 4;
                unsigned dst = bbase + (n * APAD + seg * 4) * 4;
                CPA16(dst, src, (n < NCLS) ? 16 : 0);  // rows 100..103 zero-filled
            }
        }
        asm volatile("cp.async.commit_group;\n");
    };

    load_tile(0, 0);

    for (int it = 0; it < NIT; it++) {
        asm volatile("cp.async.wait_group 0;\n");
        __syncthreads();
        if (it + 1 < NIT) load_tile((it + 1) & 1, (it + 1) * BK);

        const float* As = sm + (it & 1) * SS;
        const float* Bs = As + SA;

        if (!FIN) {
            const float* Ar = As + (tid >> 2) * APAD + (tid & 3) * 8;
#pragma unroll
            for (int i = 0; i < 8; i++) { float v = Ar[i]; qq += v * v; }
        }

#pragma unroll
        for (int step = 0; step < 4; step++) {
            const int k = step * 8 + t4;
            unsigned a[2][4];
#pragma unroll
            for (int mt = 0; mt < 2; mt++) {
                int r0 = mt * 16 + g;
                a[mt][0] = __float_as_uint(As[r0 * APAD + k]);
                a[mt][1] = __float_as_uint(As[(r0 + 8) * APAD + k]);
                a[mt][2] = __float_as_uint(As[r0 * APAD + k + 4]);
                a[mt][3] = __float_as_uint(As[(r0 + 8) * APAD + k + 4]);
            }
            unsigned b[4][2];
#pragma unroll
            for (int nt = 0; nt < 4; nt++) {
                if (wN == 3 && nt > 0) continue;       // pruned fragments
                int n0 = wN * 32 + nt * 8 + g;
                b[nt][0] = __float_as_uint(Bs[n0 * APAD + k]);
                b[nt][1] = __float_as_uint(Bs[n0 * APAD + k + 4]);
            }
#pragma unroll
            for (int mt = 0; mt < 2; mt++)
#pragma unroll
                for (int nt = 0; nt < 4; nt++) {
                    if (wN == 3 && nt > 0) continue;
                    mma_tf32(C[mt][nt], a[mt], b[nt]);
                }
        }
        __syncthreads();
    }

    if (!FIN) {
        // exact per-row sumsq -> qinv
        qq += __shfl_down_sync(0xffffffffu, qq, 1);
        qq += __shfl_down_sync(0xffffffffu, qq, 2);
        if ((tid & 3) == 0) {
            int r = tid >> 2;
            int j = j0 + r;
            float qi = 1.f / fmaxf(sqrtf(qq), EPSC);
            sq[r] = qi;
            if (j < NQ) g_qinv[j] = qi;
        }

        // stage raw dots to smem (stage-0 region is free now)
        float* pres = sm;
#pragma unroll
        for (int mt = 0; mt < 2; mt++) {
            int r0 = mt * 16 + g;
#pragma unroll
            for (int half = 0; half < 2; half++) {
                int row = r0 + half * 8;
#pragma unroll
                for (int nt = 0; nt < 4; nt++) {
                    if (wN == 3 && nt > 0) continue;
                    int c = wN * 32 + nt * 8 + 2 * t4;
                    pres[row * PSTRIDE + c]     = C[mt][nt][half * 2 + 0];
                    pres[row * PSTRIDE + c + 1] = C[mt][nt][half * 2 + 1];
                }
            }
        }
        __syncthreads();

        // fused candidate selection: warp wN scans rows wN*8..wN*8+7
#pragma unroll
        for (int r = 0; r < 8; r++) {
            int row = wN * 8 + r;
            int j = j0 + row;
            if (j >= NQ) continue;
            float v[4];
            float m = -INFINITY;
            int bi = 0x7fffffff;
#pragma unroll
            for (int t = 0; t < 4; t++) {
                int c = lane + 32 * t;
                v[t] = (c < NCLS) ? pres[row * PSTRIDE + c] : -INFINITY;
                if (v[t] > m) { m = v[t]; bi = c; }
            }
#pragma unroll
            for (int o = 16; o > 0; o >>= 1) {
                float ov = __shfl_xor_sync(0xffffffffu, m, o);
                int oi = __shfl_xor_sync(0xffffffffu, bi, o);
                if (ov > m || (ov == m && oi < bi)) { m = ov; bi = oi; }
            }
            float thr = m - GAPT_RAW;
            unsigned lml = (1u << lane) - 1u;
            int base = 0;
#pragma unroll
            for (int t = 0; t < 4; t++) {
                int c = lane + 32 * t;
                bool pred = (c < NCLS) && (v[t] >= thr);
                unsigned mask = __ballot_sync(0xffffffffu, pred);
                if (pred) {
                    int pos = base + __popc(mask & lml);
                    if (pos < MAXC) g_cand[j * MAXC + pos] = c;
                }
                base += __popc(mask);
            }
            if (lane == 0) {
                int nc = min(base, MAXC);
                g_ncand[j] = nc;
                if (nc == 1) {
                    g_label[j] = bi;
                    g_win[j] = m * sq[row];
                } else {
                    int p = atomicAdd(&g_nwork, 1);
                    g_work[p] = j;
                }
            }
        }
    } else {
        const float taov = taop[0];
#pragma unroll
        for (int mt = 0; mt < 2; mt++) {
            int r0 = mt * 16 + g;
#pragma unroll
            for (int half = 0; half < 2; half++) {
                int j = j0 + r0 + half * 8;
                if (j >= NQ) continue;
                float s = g_qinv[j] * taov;
#pragma unroll
                for (int nt = 0; nt < 4; nt++) {
                    if (wN == 3 && nt > 0) continue;
                    int c = wN * 32 + nt * 8 + 2 * t4;
                    if (c < NCLS)     out[j * NCLS + c]     = C[mt][nt][half * 2 + 0] * s;
                    if (c + 1 < NCLS) out[j * NCLS + c + 1] = C[mt][nt][half * 2 + 1] * s;
                }
            }
        }
    }
}

// ---------------- 3) exact refine: block per entry, warp per candidate ----------------
__global__ void __launch_bounds__(256) refine_kernel(const float* __restrict__ x) {
    __shared__ float sdot[MAXC];
    int nw = g_nwork;
    int w = threadIdx.x >> 5;
    int lane = threadIdx.x & 31;
    for (int t = blockIdx.x; t < nw; t += gridDim.x) {
        int j = g_work[t];
        int nc = g_ncand[j];
        const float4* q = (const float4*)(x + (size_t)qrow(j) * D);
        if (w < nc) {
            int cc = g_cand[j * MAXC + w];
            const float4* p = (const float4*)(g_pn + (size_t)cc * D);
            float d = 0.f;
#pragma unroll 4
            for (int i = lane; i < D / 4; i += 32) {
                float4 a = q[i], b = p[i];
                d += a.x * b.x + a.y * b.y + a.z * b.z + a.w * b.w;
            }
#pragma unroll
            for (int o = 16; o > 0; o >>= 1) d += __shfl_xor_sync(0xffffffffu, d, o);
            if (lane == 0) sdot[w] = d;
        }
        __syncthreads();
        if (threadIdx.x == 0) {
            float best = -INFINITY;
            int bi = 0x7fffffff;
            for (int i = 0; i < nc; i++) {
                float v = sdot[i];
                int c = g_cand[j * MAXC + i];
                if (v > best || (v == best && c < bi)) { best = v; bi = c; }
            }
            g_label[j] = bi;
            g_win[j] = best * g_qinv[j];
        }
        __syncthreads();
    }
}

// ---------------- 4) softmax weights per class ----------------
__global__ void __launch_bounds__(256) weights_kernel() {
    __shared__ int   s_off[MAXA];
    __shared__ float sred[32];
    __shared__ int   s_counts[257];

    int c = blockIdx.x, tid = threadIdx.x;

    const int chunk = (NQ + 255) / 256;
    int jlo = tid * chunk, jhi = min(NQ, jlo + chunk);
    int cnt = 0;
    for (int j = jlo; j < jhi; j++) cnt += (g_label[j] == c);
    s_counts[tid] = cnt;
    __syncthreads();
    if (tid == 0) {
        int run = 0;
        for (int i = 0; i < 256; i++) { int v = s_counts[i]; s_counts[i] = run; run += v; }
        s_counts[256] = run;
    }
    __syncthreads();
    int pos = s_counts[tid];
    for (int j = jlo; j < jhi; j++)
        if (g_label[j] == c) { if (pos < MAXA) s_off[pos] = j; pos++; }
    int total = min(s_counts[256], MAXA);
    __syncthreads();

    float m = g_self[c];
    for (int t = tid; t < total; t += 256) m = fmaxf(m, g_win[s_off[t]]);
    m = blk_max(m, sred);

    float se = 0.f;
    float ebuf[(MAXA + 255) / 256];
    for (int t = tid, r = 0; t < total; t += 256, r++) {
        float e = expf(g_win[s_off[t]] - m);
        ebuf[r] = e;
        se += e;
    }
    float eself = expf(g_self[c] - m);
    float Z = blk_sum(se, sred) + eself;
    float invZ = 1.f / Z;
    for (int t = tid, r = 0; t < total; t += 256, r++) {
        g_w[c * MAXA + t] = ebuf[r] * invZ;
        g_joff[c * MAXA + t] = qrow(s_off[t]) * D;
    }
    if (tid == 0) {
        g_cnt[c] = total;
        g_wself[c] = eself * invZ;
    }
}

// ---------------- 5) weighted sum + normalize + RNA round (fused) ----------------
__global__ void __launch_bounds__(1024) wsum_norm_kernel(const float* __restrict__ x) {
    __shared__ float sred[32];
    __shared__ float sw[MAXA];
    __shared__ int   soff[MAXA];
    int c = blockIdx.x;
    int tid = threadIdx.x;
    int dim = tid * 4;
    int total = g_cnt[c];

    for (int i = tid; i < total; i += 1024) {
        sw[i] = g_w[c * MAXA + i];
        soff[i] = g_joff[c * MAXA + i];
    }
    __syncthreads();

    float4 a0 = make_float4(0.f, 0.f, 0.f, 0.f);
    float4 a1 = make_float4(0.f, 0.f, 0.f, 0.f);
    float4 a2 = make_float4(0.f, 0.f, 0.f, 0.f);
    float4 a3 = make_float4(0.f, 0.f, 0.f, 0.f);
    int t = 0;
    for (; t + 4 <= total; t += 4) {
        float w0 = sw[t], w1 = sw[t + 1], w2 = sw[t + 2], w3 = sw[t + 3];
        float4 v0 = *(const float4*)(x + soff[t] + dim);
        float4 v1 = *(const float4*)(x + soff[t + 1] + dim);
        float4 v2 = *(const float4*)(x + soff[t + 2] + dim);
        float4 v3 = *(const float4*)(x + soff[t + 3] + dim);
        a0.x += w0 * v0.x; a0.y += w0 * v0.y; a0.z += w0 * v0.z; a0.w += w0 * v0.w;
        a1.x += w1 * v1.x; a1.y += w1 * v1.y; a1.z += w1 * v1.z; a1.w += w1 * v1.w;
        a2.x += w2 * v2.x; a2.y += w2 * v2.y; a2.z += w2 * v2.z; a2.w += w2 * v2.w;
        a3.x += w3 * v3.x; a3.y += w3 * v3.y; a3.z += w3 * v3.z; a3.w += w3 * v3.w;
    }
    for (; t < total; t++) {
        float w = sw[t];
        float4 v = *(const float4*)(x + soff[t] + dim);
        a0.x += w * v.x; a0.y += w * v.y; a0.z += w * v.z; a0.w += w * v.w;
    }
    float wself = g_wself[c];
    float4 pr = *(const float4*)(g_proto + (size_t)c * D + dim);
    float4 acc;
    acc.x = a0.x + a1.x + a2.x + a3.x + wself * pr.x;
    acc.y = a0.y + a1.y + a2.y + a3.y + wself * pr.y;
    acc.z = a0.z + a1.z + a2.z + a3.z + wself * pr.z;
    acc.w = a0.w + a1.w + a2.w + a3.w + wself * pr.w;
    float ss = acc.x * acc.x + acc.y * acc.y + acc.z * acc.z + acc.w * acc.w;
    float tot = blk_sum(ss, sred);
    float inv = 1.f / fmaxf(sqrtf(tot), EPSC);
    float4 r;
    r.x = f2tff(acc.x * inv); r.y = f2tff(acc.y * inv);
    r.z = f2tff(acc.z * inv); r.w = f2tff(acc.w * inv);
    *(float4*)(g_anh + (size_t)c * D + dim) = r;
}

// ---------------- launch ----------------
extern "C" void kernel_launch(void* const* d_in, const int* in_sizes, int n_in,
                              void* d_out, int out_size) {
    const float* x   = (const float*)d_in[0];
    const float* tao = (const float*)d_in[1];
    float* out = (float*)d_out;

    float *pnh, *anh;
    cudaGetSymbolAddress((void**)&pnh, g_pnh);
    cudaGetSymbolAddress((void**)&anh, g_anh);

    const int smem = 2 * (BM * APAD + BNROWS * APAD) * 4;   // 39168 B
    const int nblk = (NQ + BM - 1) / BM;                    // 235

    proto_kernel<<<NCLS, 1024>>>(x);
    mma_gemm<0><<<nblk, 128, smem>>>(x, pnh, tao, out);     // out unused in FIN=0
    refine_kernel<<<256, 256>>>(x);
    weights_kernel<<<NCLS, 256>>>();
    wsum_norm_kernel<<<NCLS, 1024>>>(x);
    mma_gemm<1><<<nblk, 128, smem>>>(x, anh, tao, out);
}